// round 2
// baseline (speedup 1.0000x reference)
#include <cuda_runtime.h>
#include <math.h>

#define BB 32
#define TT 64
#define NT 2048        // BB*TT images
#define KSPLIT 8
#define KC 2048        // K-chunk per split (8*2048 = 16384)

// Scratch (static device globals — allocation-free kernel_launch)
__device__ float g_act1[(size_t)NT * 32 * 32 * 32];   // conv1 out: [n][32][32][32]
__device__ float g_feats[(size_t)NT * 16384];         // conv2 out: [n][c*256+y*16+x]
__device__ float g_prep[(size_t)KSPLIT * NT * 128];   // split-K partials of feats @ bb_w[:16384]

// ---------------------------------------------------------------------------
// conv1: (n,3,64,64) -> relu -> (n,32,32,32), k=4 s=2 p=1. One CTA per image.
// ---------------------------------------------------------------------------
__global__ void conv1_kernel(const float* __restrict__ x,
                             const float* __restrict__ w,
                             const float* __restrict__ bias) {
    extern __shared__ float sm[];
    float* ws = sm;              // [48][32]  (icc-major, oc contiguous for float4)
    float* bs = ws + 48 * 32;    // [32]
    float* in = bs + 32;         // [3][66][66] zero-padded
    const int n = blockIdx.x, tid = threadIdx.x;

    for (int t = tid; t < 48 * 32; t += 256) {
        int oc = t / 48, icc = t % 48;          // global layout [oc][ic][ky][kx]
        ws[icc * 32 + oc] = w[t];
    }
    if (tid < 32) bs[tid] = bias[tid];
    for (int t = tid; t < 3 * 66 * 66; t += 256) in[t] = 0.f;
    __syncthreads();

    const float* xg = x + (size_t)n * 3 * 64 * 64;
    for (int t = tid; t < 3 * 64 * 64; t += 256) {
        int ic = t >> 12, r = t & 4095, y = r >> 6, xx = r & 63;
        in[ic * 4356 + (y + 1) * 66 + (xx + 1)] = xg[t];
    }
    __syncthreads();

    float* outg = g_act1 + (size_t)n * 32768;
    for (int p = tid; p < 1024; p += 256) {
        int y = p >> 5, xx = p & 31;
        float acc[32];
#pragma unroll
        for (int o = 0; o < 32; o++) acc[o] = 0.f;
        for (int ic = 0; ic < 3; ic++) {
#pragma unroll
            for (int ky = 0; ky < 4; ky++) {
                const float* row = &in[ic * 4356 + (2 * y + ky) * 66 + 2 * xx];
#pragma unroll
                for (int kx = 0; kx < 4; kx++) {
                    float v = row[kx];
                    const float4* w4 = (const float4*)&ws[(ic * 16 + ky * 4 + kx) * 32];
#pragma unroll
                    for (int q = 0; q < 8; q++) {
                        float4 wv = w4[q];
                        acc[q * 4 + 0] += v * wv.x;
                        acc[q * 4 + 1] += v * wv.y;
                        acc[q * 4 + 2] += v * wv.z;
                        acc[q * 4 + 3] += v * wv.w;
                    }
                }
            }
        }
#pragma unroll
        for (int o = 0; o < 32; o++) outg[o * 1024 + p] = fmaxf(acc[o] + bs[o], 0.f);
    }
}

// ---------------------------------------------------------------------------
// conv2: (n,32,32,32) -> relu -> (n,64,16,16). CTA = (image, 16-oc group).
// ---------------------------------------------------------------------------
__global__ void conv2_kernel(const float* __restrict__ w,
                             const float* __restrict__ bias) {
    extern __shared__ float sm[];
    float* ws = sm;               // [512][16]
    float* bs = ws + 512 * 16;    // [16]
    float* in = bs + 16;          // [32][34][34] zero-padded
    const int n = blockIdx.x, ocg = blockIdx.y, tid = threadIdx.x;

    for (int t = tid; t < 512 * 16; t += 256) {
        int o = t >> 9, icc = t & 511;          // global layout [oc][ic][ky][kx]
        ws[icc * 16 + o] = w[(ocg * 16 + o) * 512 + icc];
    }
    if (tid < 16) bs[tid] = bias[ocg * 16 + tid];
    for (int t = tid; t < 32 * 1156; t += 256) in[t] = 0.f;
    __syncthreads();

    const float* xg = g_act1 + (size_t)n * 32768;
    for (int t = tid; t < 32768; t += 256) {
        int ic = t >> 10, r = t & 1023, y = r >> 5, xx = r & 31;
        in[ic * 1156 + (y + 1) * 34 + (xx + 1)] = xg[t];
    }
    __syncthreads();

    const int y = tid >> 4, xx = tid & 15;      // 16x16 spatial, one pos/thread
    float acc[16];
#pragma unroll
    for (int o = 0; o < 16; o++) acc[o] = 0.f;
    for (int ic = 0; ic < 32; ic++) {
#pragma unroll
        for (int ky = 0; ky < 4; ky++) {
            const float* row = &in[ic * 1156 + (2 * y + ky) * 34 + 2 * xx];
#pragma unroll
            for (int kx = 0; kx < 4; kx++) {
                float v = row[kx];
                const float4* w4 = (const float4*)&ws[(ic * 16 + ky * 4 + kx) * 16];
#pragma unroll
                for (int q = 0; q < 4; q++) {
                    float4 wv = w4[q];
                    acc[q * 4 + 0] += v * wv.x;
                    acc[q * 4 + 1] += v * wv.y;
                    acc[q * 4 + 2] += v * wv.z;
                    acc[q * 4 + 3] += v * wv.w;
                }
            }
        }
    }
    float* outg = g_feats + (size_t)n * 16384 + ocg * 16 * 256;
#pragma unroll
    for (int o = 0; o < 16; o++) outg[o * 256 + tid] = fmaxf(acc[o] + bs[o], 0.f);
}

// ---------------------------------------------------------------------------
// Split-K GEMM: g_prep[s] += feats(2048 x KC-chunk) @ bb_w-chunk (128 cols).
// Grid (32 M-tiles of 64, KSPLIT). Deterministic (no atomics).
// ---------------------------------------------------------------------------
__global__ void gemm_pre_kernel(const float* __restrict__ bbw) {
    __shared__ float As[32][68];   // [kk][mm], padded (272B rows, 16B aligned)
    __shared__ float Bs[32][132];  // [kk][nn], padded (528B rows, 16B aligned)
    const int tid = threadIdx.x;
    const int tx = tid & 15, ty = tid >> 4;
    const int m0 = blockIdx.x * 64;
    const int k00 = blockIdx.y * KC;

    float acc[4][8];
#pragma unroll
    for (int i = 0; i < 4; i++)
#pragma unroll
        for (int j = 0; j < 8; j++) acc[i][j] = 0.f;

    const int mmL = tid & 63, kaL = (tid >> 6) * 8;     // A loader mapping
    const int kbL = tid & 31, nbL = (tid >> 5) * 16;    // B loader mapping

    for (int kt = 0; kt < KC; kt += 32) {
        const float* ag = g_feats + (size_t)(m0 + mmL) * 16384 + k00 + kt + kaL;
#pragma unroll
        for (int i = 0; i < 8; i++) As[kaL + i][mmL] = ag[i];
        const float* bg = bbw + (size_t)(k00 + kt + kbL) * 128 + nbL;
#pragma unroll
        for (int i = 0; i < 16; i += 4)
            *(float4*)&Bs[kbL][nbL + i] = *(const float4*)&bg[i];
        __syncthreads();

#pragma unroll
        for (int kk = 0; kk < 32; kk++) {
            float4 a4 = *(const float4*)&As[kk][ty * 4];
            float bvals[8];
            *(float4*)&bvals[0] = *(const float4*)&Bs[kk][tx * 8];
            *(float4*)&bvals[4] = *(const float4*)&Bs[kk][tx * 8 + 4];
            float avals[4] = {a4.x, a4.y, a4.z, a4.w};
#pragma unroll
            for (int i = 0; i < 4; i++)
#pragma unroll
                for (int j = 0; j < 8; j++) acc[i][j] += avals[i] * bvals[j];
        }
        __syncthreads();
    }

    float* outp = g_prep + (size_t)blockIdx.y * NT * 128;
#pragma unroll
    for (int i = 0; i < 4; i++)
#pragma unroll
        for (int j = 0; j < 8; j++)
            outp[(size_t)(m0 + ty * 4 + i) * 128 + tx * 8 + j] = acc[i][j];
}

// ---------------------------------------------------------------------------
// CfC recurrent scan + logits. One CTA per batch element, all weights in SMEM.
// ---------------------------------------------------------------------------
__global__ void recur_kernel(const float* __restrict__ hx,
                             const float* __restrict__ bbw,
                             const float* __restrict__ bbb,
                             const float* __restrict__ f1w, const float* __restrict__ f1b,
                             const float* __restrict__ f2w, const float* __restrict__ f2b,
                             const float* __restrict__ taw, const float* __restrict__ tab,
                             const float* __restrict__ tbw, const float* __restrict__ tbb,
                             const float* __restrict__ ow,  const float* __restrict__ ob,
                             float* __restrict__ out, int out_size) {
    extern __shared__ float sm[];
    float* wh    = sm;                  // [128][68]   bb_w h-rows, j-major
    float* whead = wh + 128 * 68;       // [256][132]  4 head mats, o-major
    float* outw  = whead + 256 * 132;   // [8][68]
    float* bbbs  = outw + 8 * 68;       // [128]
    float* hbs   = bbbs + 128;          // [256]
    float* obs   = hbs + 256;           // [8]
    float* hs    = obs + 8;             // [64]
    float* bbs   = hs + 64;             // [128]
    float* heads = bbs + 128;           // [256]
    float* outs  = heads + 256;         // [64][68]
    const int b = blockIdx.x, tid = threadIdx.x;

    for (int t = tid; t < 128 * 64; t += 256) {
        int j = t >> 6, k = t & 63;
        wh[j * 68 + k] = bbw[(size_t)(16384 + k) * 128 + j];
    }
    for (int t = tid; t < 4 * 64 * 128; t += 256) {
        int m = t >> 13, r = t & 8191, i = r >> 7, k = r & 127;
        const float* W = (m == 0) ? f1w : (m == 1) ? f2w : (m == 2) ? taw : tbw;
        whead[(m * 64 + i) * 132 + k] = W[k * 64 + i];
    }
    for (int t = tid; t < 512; t += 256) {
        int i = t >> 3, o = t & 7;
        outw[o * 68 + i] = ow[t];
    }
    if (tid < 128) bbbs[tid] = bbb[tid];
    {
        int m = tid >> 6, i = tid & 63;
        hbs[tid] = (m == 0) ? f1b[i] : (m == 1) ? f2b[i] : (m == 2) ? tab[i] : tbb[i];
    }
    if (tid < 8)  obs[tid] = ob[tid];
    if (tid < 64) hs[tid] = hx[b * 64 + tid];
    __syncthreads();

    for (int ts = 0; ts < TT; ts++) {
        // phase 0: bb = lecun_tanh(pre + h @ Wh)
        if (tid < 128) {
            float acc = bbbs[tid];
            size_t base = (size_t)(b * TT + ts) * 128 + tid;
#pragma unroll
            for (int s = 0; s < KSPLIT; s++) acc += g_prep[(size_t)s * NT * 128 + base];
            const float4* w4 = (const float4*)&wh[tid * 68];
            const float4* h4 = (const float4*)hs;
#pragma unroll
            for (int k4 = 0; k4 < 16; k4++) {
                float4 wv = w4[k4], hv = h4[k4];
                acc += wv.x * hv.x + wv.y * hv.y + wv.z * hv.z + wv.w * hv.w;
            }
            bbs[tid] = 1.7159f * tanhf(0.666f * acc);
        }
        __syncthreads();
        // phase 1: 4 head projections (ff1/ff2 tanh'd; ta/tb linear)
        {
            float acc = hbs[tid];
            const float4* w4 = (const float4*)&whead[tid * 132];
            const float4* b4 = (const float4*)bbs;
#pragma unroll
            for (int k4 = 0; k4 < 32; k4++) {
                float4 wv = w4[k4], bv = b4[k4];
                acc += wv.x * bv.x + wv.y * bv.y + wv.z * bv.z + wv.w * bv.w;
            }
            if (tid < 128) acc = tanhf(acc);
            heads[tid] = acc;
        }
        __syncthreads();
        // phase 2: gated interpolation
        if (tid < 64) {
            float ti = 1.f / (1.f + expf(-(heads[128 + tid] + heads[192 + tid])));
            float hn = heads[tid] * (1.f - ti) + ti * heads[64 + tid];
            hs[tid] = hn;
            outs[ts * 68 + tid] = hn;
        }
        __syncthreads();
    }

    // logits epilogue: (64 steps x 8) outputs
    for (int t = tid; t < 512; t += 256) {
        int s = t >> 3, o = t & 7;
        float acc = obs[o];
        const float* r = &outs[s * 68];
        const float* wv = &outw[o * 68];
#pragma unroll
        for (int i = 0; i < 64; i++) acc += r[i] * wv[i];
        out[(size_t)(b * TT + s) * 8 + o] = acc;
    }
    if (out_size >= 18432 && tid < 64) out[16384 + b * 64 + tid] = hs[tid];
}

// ---------------------------------------------------------------------------
extern "C" void kernel_launch(void* const* d_in, const int* in_sizes, int n_in,
                              void* d_out, int out_size) {
    const float* x_vis   = (const float*)d_in[0];
    const float* hx      = (const float*)d_in[1];
    const float* conv1_w = (const float*)d_in[2];
    const float* conv1_b = (const float*)d_in[3];
    const float* conv2_w = (const float*)d_in[4];
    const float* conv2_b = (const float*)d_in[5];
    const float* bb_w    = (const float*)d_in[6];
    const float* bb_b    = (const float*)d_in[7];
    const float* ff1_w   = (const float*)d_in[8];
    const float* ff1_b   = (const float*)d_in[9];
    const float* ff2_w   = (const float*)d_in[10];
    const float* ff2_b   = (const float*)d_in[11];
    const float* ta_w    = (const float*)d_in[12];
    const float* ta_b    = (const float*)d_in[13];
    const float* tb_w    = (const float*)d_in[14];
    const float* tb_b    = (const float*)d_in[15];
    const float* out_w   = (const float*)d_in[16];
    const float* out_b   = (const float*)d_in[17];
    float* out = (float*)d_out;

    const size_t sm1 = (size_t)(48 * 32 + 32 + 3 * 66 * 66) * sizeof(float);      // ~58.5 KB
    const size_t sm2 = (size_t)(512 * 16 + 16 + 32 * 1156) * sizeof(float);       // ~180.8 KB
    const size_t smr = (size_t)48232 * sizeof(float);                             // ~192.9 KB

    cudaFuncSetAttribute(conv1_kernel, cudaFuncAttributeMaxDynamicSharedMemorySize, (int)sm1);
    cudaFuncSetAttribute(conv2_kernel, cudaFuncAttributeMaxDynamicSharedMemorySize, (int)sm2);
    cudaFuncSetAttribute(recur_kernel, cudaFuncAttributeMaxDynamicSharedMemorySize, (int)smr);

    conv1_kernel<<<NT, 256, sm1>>>(x_vis, conv1_w, conv1_b);
    conv2_kernel<<<dim3(NT, 4), 256, sm2>>>(conv2_w, conv2_b);
    gemm_pre_kernel<<<dim3(32, KSPLIT), 256>>>(bb_w);
    recur_kernel<<<BB, 256, smr>>>(hx, bb_w, bb_b,
                                   ff1_w, ff1_b, ff2_w, ff2_b,
                                   ta_w, ta_b, tb_w, tb_b,
                                   out_w, out_b, out, out_size);
}

// round 3
// speedup vs baseline: 5.2014x; 5.2014x over previous
#include <cuda_runtime.h>
#include <math.h>

#define BB 32
#define TT 64
#define NT 2048        // BB*TT images
#define KSPLIT 8

// Scratch (static device globals — allocation-free kernel_launch)
__device__ float g_feats[(size_t)NT * 16384];         // conv2 out (tf32-rounded): [n][oc*256+p]
__device__ float g_prep[(size_t)KSPLIT * NT * 128];   // split-K partials
__device__ float g_prepr[(size_t)NT * 128];           // reduced partials
__device__ float w1t[48 * 32];                        // conv1 w, [icc][oc], tf32-rounded
__device__ float w2t[512 * 64];                       // conv2 w, [icc][oc], tf32-rounded

// ---------------------------------------------------------------------------
// helpers
// ---------------------------------------------------------------------------
__device__ __forceinline__ unsigned cvt_tf32(float x) {
    unsigned u;
    asm("cvt.rna.tf32.f32 %0, %1;" : "=r"(u) : "f"(x));
    return u;
}
__device__ __forceinline__ float tf32f(float x) { return __uint_as_float(cvt_tf32(x)); }
__device__ __forceinline__ unsigned f2u(float x) { return __float_as_uint(x); }

#define MMA_TF32(d, a0, a1, a2, a3, b0, b1)                                   \
    asm volatile("mma.sync.aligned.m16n8k8.row.col.f32.tf32.tf32.f32 "        \
                 "{%0,%1,%2,%3}, {%4,%5,%6,%7}, {%8,%9}, {%0,%1,%2,%3};"      \
                 : "+f"(d[0]), "+f"(d[1]), "+f"(d[2]), "+f"(d[3])             \
                 : "r"(a0), "r"(a1), "r"(a2), "r"(a3), "r"(b0), "r"(b1))

__device__ __forceinline__ float fast_tanh(float x) {
    float e = __expf(2.f * x);
    return 1.f - __fdividef(2.f, e + 1.f);
}
__device__ __forceinline__ float fast_sig(float x) {
    return __fdividef(1.f, 1.f + __expf(-x));
}

// ---------------------------------------------------------------------------
// prep: transpose + tf32-round conv weights
// ---------------------------------------------------------------------------
__global__ void prep_kernel(const float* __restrict__ w1, const float* __restrict__ w2) {
    int i = blockIdx.x * blockDim.x + threadIdx.x;
    if (i < 1536) {
        int oc = i / 48, c = i % 48;
        w1t[c * 32 + oc] = tf32f(w1[i]);
    }
    if (i < 32768) {
        int oc = i >> 9, c = i & 511;
        w2t[c * 64 + oc] = tf32f(w2[i]);
    }
}

// ---------------------------------------------------------------------------
// Fused conv1+conv2 per image, tf32 mma. One CTA per image, 512 threads.
// SMEM (floats): act_pad[32][34][34] | union{x_pad[3][66][66], Bs2[128][72]} |
//                Bs1[48][40] | p1tab[48] | p2tab[512] | bias1[32] | bias2[64]
// ---------------------------------------------------------------------------
#define OFF_ACT 0
#define OFF_XW  36992
#define OFF_B1  50060
#define OFF_P1  51980
#define OFF_P2  52028
#define OFF_BI1 52540
#define OFF_BI2 52572
#define SMF_FLOATS 52636

__global__ __launch_bounds__(512, 1) void fused_conv_kernel(
    const float* __restrict__ x_vis,
    const float* __restrict__ b1g, const float* __restrict__ b2g) {
    extern __shared__ float sm[];
    float* act_s = sm + OFF_ACT;
    float* xs    = sm + OFF_XW;   // x_pad during conv1, Bs2 during conv2
    float* bs1   = sm + OFF_B1;
    int*   p1t   = (int*)(sm + OFF_P1);
    int*   p2t   = (int*)(sm + OFF_P2);
    float* bi1   = sm + OFF_BI1;
    float* bi2   = sm + OFF_BI2;

    const int n = blockIdx.x, tid = threadIdx.x;
    const int lane = tid & 31, w = tid >> 5;
    const int tig = lane & 3, gid = lane >> 2;

    // zero act_pad + x_pad
    for (int t = tid; t < 50060; t += 512) sm[t] = 0.f;
    // tables
    if (tid < 48) {
        int ic = tid >> 4, ky = (tid >> 2) & 3, kx = tid & 3;
        p1t[tid] = ic * 4356 + ky * 66 + kx;
    }
    if (tid < 512) {
        int ic = tid >> 4, ky = (tid >> 2) & 3, kx = tid & 3;
        p2t[tid] = ic * 1156 + ky * 34 + kx;
    }
    for (int t = tid; t < 1536; t += 512) bs1[(t >> 5) * 40 + (t & 31)] = w1t[t];
    if (tid < 32) bi1[tid] = b1g[tid];
    if (tid < 64) bi2[tid] = b2g[tid];
    __syncthreads();

    // load x (tf32-rounded) into padded smem
    const float* xg = x_vis + (size_t)n * 12288;
    for (int t = tid; t < 12288; t += 512) {
        int ic = t >> 12, r = t & 4095, y = r >> 6, xx = r & 63;
        xs[ic * 4356 + (y + 1) * 66 + xx + 1] = tf32f(xg[t]);
    }
    __syncthreads();

    // ---- conv1: M=1024, N=32, K=48 ----
    {
        float acc1[4][4][4];
#pragma unroll
        for (int a = 0; a < 4; a++)
#pragma unroll
            for (int b = 0; b < 4; b++)
#pragma unroll
                for (int c = 0; c < 4; c++) acc1[a][b][c] = 0.f;
        int pbl[4], pbh[4];
#pragma unroll
        for (int mt = 0; mt < 4; mt++) {
            int pl = w * 64 + mt * 16 + gid, ph = pl + 8;
            pbl[mt] = ((pl >> 5) * 2) * 66 + (pl & 31) * 2;
            pbh[mt] = ((ph >> 5) * 2) * 66 + (ph & 31) * 2;
        }
#pragma unroll
        for (int ks = 0; ks < 6; ks++) {
            int c0 = ks * 8 + tig, c1 = c0 + 4;
            int off0 = p1t[c0], off1 = p1t[c1];
            unsigned b0[4], b1[4];
#pragma unroll
            for (int nt = 0; nt < 4; nt++) {
                b0[nt] = f2u(bs1[c0 * 40 + nt * 8 + gid]);
                b1[nt] = f2u(bs1[c1 * 40 + nt * 8 + gid]);
            }
#pragma unroll
            for (int mt = 0; mt < 4; mt++) {
                unsigned a0 = f2u(xs[off0 + pbl[mt]]);
                unsigned a1 = f2u(xs[off0 + pbh[mt]]);
                unsigned a2 = f2u(xs[off1 + pbl[mt]]);
                unsigned a3 = f2u(xs[off1 + pbh[mt]]);
#pragma unroll
                for (int nt = 0; nt < 4; nt++)
                    MMA_TF32(acc1[mt][nt], a0, a1, a2, a3, b0[nt], b1[nt]);
            }
        }
        // epilogue: relu+bias -> tf32 -> padded act smem [oc][y+1][x+1]
#pragma unroll
        for (int mt = 0; mt < 4; mt++) {
            int pl = w * 64 + mt * 16 + gid, ph = pl + 8;
            int yl = ((pl >> 5) + 1) * 34 + (pl & 31) + 1;
            int yh = ((ph >> 5) + 1) * 34 + (ph & 31) + 1;
#pragma unroll
            for (int nt = 0; nt < 4; nt++) {
                int oc = nt * 8 + 2 * tig;
                act_s[oc * 1156 + yl]       = tf32f(fmaxf(acc1[mt][nt][0] + bi1[oc], 0.f));
                act_s[(oc + 1) * 1156 + yl] = tf32f(fmaxf(acc1[mt][nt][1] + bi1[oc + 1], 0.f));
                act_s[oc * 1156 + yh]       = tf32f(fmaxf(acc1[mt][nt][2] + bi1[oc], 0.f));
                act_s[(oc + 1) * 1156 + yh] = tf32f(fmaxf(acc1[mt][nt][3] + bi1[oc + 1], 0.f));
            }
        }
    }

    // ---- conv2: M=256, N=64, K=512 (4 chunks of 128 icc) ----
    {
        float acc2[8][4];
#pragma unroll
        for (int a = 0; a < 8; a++)
#pragma unroll
            for (int c = 0; c < 4; c++) acc2[a][c] = 0.f;
        const int pl = w * 16 + gid, ph = pl + 8;
        const int pbl = ((pl >> 4) * 2) * 34 + (pl & 15) * 2;
        const int pbh = ((ph >> 4) * 2) * 34 + (ph & 15) * 2;

        for (int icg = 0; icg < 4; icg++) {
            __syncthreads();   // act writes done (icg=0) / prev chunk consumed
            // stage Bs2 chunk [128][72] from w2t
#pragma unroll
            for (int j = 0; j < 4; j++) {
                int idx = tid * 4 + j * 2048;
                int row = idx >> 6, col = idx & 63;
                *(float4*)&xs[row * 72 + col] =
                    *(const float4*)&w2t[(icg * 128 + row) * 64 + col];
            }
            __syncthreads();
#pragma unroll
            for (int ks = 0; ks < 16; ks++) {
                int ck0 = ks * 8 + tig, ck1 = ck0 + 4;
                int off0 = p2t[icg * 128 + ck0], off1 = p2t[icg * 128 + ck1];
                unsigned a0 = f2u(act_s[off0 + pbl]);
                unsigned a1 = f2u(act_s[off0 + pbh]);
                unsigned a2 = f2u(act_s[off1 + pbl]);
                unsigned a3 = f2u(act_s[off1 + pbh]);
#pragma unroll
                for (int nt = 0; nt < 8; nt++) {
                    unsigned b0 = f2u(xs[ck0 * 72 + nt * 8 + gid]);
                    unsigned b1 = f2u(xs[ck1 * 72 + nt * 8 + gid]);
                    MMA_TF32(acc2[nt], a0, a1, a2, a3, b0, b1);
                }
            }
        }
        // epilogue -> g_feats (tf32-rounded for the GEMM A)
        float* fo = g_feats + (size_t)n * 16384;
#pragma unroll
        for (int nt = 0; nt < 8; nt++) {
            int oc = nt * 8 + 2 * tig;
            fo[oc * 256 + pl]       = tf32f(fmaxf(acc2[nt][0] + bi2[oc], 0.f));
            fo[(oc + 1) * 256 + pl] = tf32f(fmaxf(acc2[nt][1] + bi2[oc + 1], 0.f));
            fo[oc * 256 + ph]       = tf32f(fmaxf(acc2[nt][2] + bi2[oc], 0.f));
            fo[(oc + 1) * 256 + ph] = tf32f(fmaxf(acc2[nt][3] + bi2[oc + 1], 0.f));
        }
    }
}

// ---------------------------------------------------------------------------
// tf32 GEMM: g_prep[s] = feats(2048 x 2048-chunk) @ bb_w-chunk (128 cols).
// Grid (16 M-tiles of 128, KSPLIT). Register-prefetch double buffering.
// ---------------------------------------------------------------------------
__global__ __launch_bounds__(256, 2) void gemm_pre_kernel(const float* __restrict__ bbw) {
    __shared__ float As[128 * 36];
    __shared__ float Bs[32 * 136];
    const int tid = threadIdx.x, lane = tid & 31, w = tid >> 5;
    const int tig = lane & 3, gid = lane >> 2;
    const int m0 = blockIdx.x * 128;
    const size_t kb = (size_t)blockIdx.y * 2048;
    const int ar = tid >> 3, ac = (tid & 7) * 4;
    const int br = tid >> 5, bc = (tid & 31) * 4;

    float4 pa[4], pb[4];
    float acc[16][4];
#pragma unroll
    for (int a = 0; a < 16; a++)
#pragma unroll
        for (int c = 0; c < 4; c++) acc[a][c] = 0.f;

#define LD_TILES(kt)                                                           \
    {                                                                          \
        _Pragma("unroll") for (int j = 0; j < 4; j++)                          \
            pa[j] = *(const float4*)&g_feats[(size_t)(m0 + ar + j * 32) * 16384 + kb + (kt) + ac]; \
        _Pragma("unroll") for (int j = 0; j < 4; j++)                          \
            pb[j] = *(const float4*)&bbw[(kb + (kt) + br + j * 8) * 128 + bc]; \
    }
#define ST_TILES()                                                             \
    {                                                                          \
        _Pragma("unroll") for (int j = 0; j < 4; j++)                          \
            *(float4*)&As[(ar + j * 32) * 36 + ac] = pa[j];                    \
        _Pragma("unroll") for (int j = 0; j < 4; j++) {                        \
            float4 v = pb[j];                                                  \
            v.x = tf32f(v.x); v.y = tf32f(v.y); v.z = tf32f(v.z); v.w = tf32f(v.w); \
            *(float4*)&Bs[(br + j * 8) * 136 + bc] = v;                        \
        }                                                                      \
    }

    LD_TILES(0);
    ST_TILES();
    __syncthreads();

    for (int it = 0; it < 64; it++) {
        if (it < 63) LD_TILES((it + 1) * 32);
#pragma unroll
        for (int ks = 0; ks < 4; ks++) {
            int k0 = ks * 8;
            unsigned a0 = f2u(As[(w * 16 + gid) * 36 + k0 + tig]);
            unsigned a1 = f2u(As[(w * 16 + gid + 8) * 36 + k0 + tig]);
            unsigned a2 = f2u(As[(w * 16 + gid) * 36 + k0 + tig + 4]);
            unsigned a3 = f2u(As[(w * 16 + gid + 8) * 36 + k0 + tig + 4]);
#pragma unroll
            for (int nt = 0; nt < 16; nt++) {
                unsigned b0 = f2u(Bs[(k0 + tig) * 136 + nt * 8 + gid]);
                unsigned b1 = f2u(Bs[(k0 + tig + 4) * 136 + nt * 8 + gid]);
                MMA_TF32(acc[nt], a0, a1, a2, a3, b0, b1);
            }
        }
        __syncthreads();
        if (it < 63) {
            ST_TILES();
            __syncthreads();
        }
    }

    float* op = g_prep + (size_t)blockIdx.y * (NT * 128);
    const int r0 = m0 + w * 16 + gid;
#pragma unroll
    for (int nt = 0; nt < 16; nt++) {
        *(float2*)&op[(size_t)r0 * 128 + nt * 8 + 2 * tig] = make_float2(acc[nt][0], acc[nt][1]);
        *(float2*)&op[(size_t)(r0 + 8) * 128 + nt * 8 + 2 * tig] = make_float2(acc[nt][2], acc[nt][3]);
    }
}

// ---------------------------------------------------------------------------
// reduce split-K partials: g_prepr = sum_s g_prep[s]
// ---------------------------------------------------------------------------
__global__ void reduce_kernel() {
    int i = blockIdx.x * 256 + threadIdx.x;   // over 65536 float4
    const float4* src = (const float4*)g_prep;
    float4 a = src[i];
#pragma unroll
    for (int s = 1; s < KSPLIT; s++) {
        float4 b = src[(size_t)s * 65536 + i];
        a.x += b.x; a.y += b.y; a.z += b.z; a.w += b.w;
    }
    ((float4*)g_prepr)[i] = a;
}

// ---------------------------------------------------------------------------
// CfC recurrent scan + logits. One CTA per batch element, weights in SMEM.
// ---------------------------------------------------------------------------
__global__ void recur_kernel(const float* __restrict__ hx,
                             const float* __restrict__ bbw,
                             const float* __restrict__ bbb,
                             const float* __restrict__ f1w, const float* __restrict__ f1b,
                             const float* __restrict__ f2w, const float* __restrict__ f2b,
                             const float* __restrict__ taw, const float* __restrict__ tab,
                             const float* __restrict__ tbw, const float* __restrict__ tbb,
                             const float* __restrict__ ow,  const float* __restrict__ ob,
                             float* __restrict__ out, int out_size) {
    extern __shared__ float sm[];
    float* wh    = sm;                  // [128][68]   bb_w h-rows, j-major
    float* whead = wh + 128 * 68;       // [256][132]  4 head mats, o-major
    float* outw  = whead + 256 * 132;   // [8][68]
    float* bbbs  = outw + 8 * 68;       // [128]
    float* hbs   = bbbs + 128;          // [256]
    float* obs   = hbs + 256;           // [8]
    float* hs    = obs + 8;             // [64]
    float* bbs   = hs + 64;             // [128]
    float* heads = bbs + 128;           // [256]
    float* outs  = heads + 256;         // [64][68]
    const int b = blockIdx.x, tid = threadIdx.x;

    for (int t = tid; t < 128 * 64; t += 256) {
        int j = t >> 6, k = t & 63;
        wh[j * 68 + k] = bbw[(size_t)(16384 + k) * 128 + j];
    }
    for (int t = tid; t < 4 * 64 * 128; t += 256) {
        int m = t >> 13, r = t & 8191, i = r >> 7, k = r & 127;
        const float* W = (m == 0) ? f1w : (m == 1) ? f2w : (m == 2) ? taw : tbw;
        whead[(m * 64 + i) * 132 + k] = W[k * 64 + i];
    }
    for (int t = tid; t < 512; t += 256) {
        int i = t >> 3, o = t & 7;
        outw[o * 68 + i] = ow[t];
    }
    if (tid < 128) bbbs[tid] = bbb[tid];
    {
        int m = tid >> 6, i = tid & 63;
        hbs[tid] = (m == 0) ? f1b[i] : (m == 1) ? f2b[i] : (m == 2) ? tab[i] : tbb[i];
    }
    if (tid < 8)  obs[tid] = ob[tid];
    if (tid < 64) hs[tid] = hx[b * 64 + tid];
    __syncthreads();

    float nxt = (tid < 128) ? g_prepr[(size_t)(b * TT) * 128 + tid] : 0.f;

    for (int ts = 0; ts < TT; ts++) {
        float cur = nxt;
        if (ts < TT - 1 && tid < 128)
            nxt = g_prepr[(size_t)(b * TT + ts + 1) * 128 + tid];  // prefetch next step
        // phase 0: bb = lecun_tanh(pre + h @ Wh)
        if (tid < 128) {
            float a0 = bbbs[tid] + cur, a1 = 0.f;
            const float4* w4 = (const float4*)&wh[tid * 68];
            const float4* h4 = (const float4*)hs;
#pragma unroll
            for (int k4 = 0; k4 < 16; k4 += 2) {
                float4 wv = w4[k4], hv = h4[k4];
                a0 += wv.x * hv.x + wv.y * hv.y + wv.z * hv.z + wv.w * hv.w;
                float4 wv2 = w4[k4 + 1], hv2 = h4[k4 + 1];
                a1 += wv2.x * hv2.x + wv2.y * hv2.y + wv2.z * hv2.z + wv2.w * hv2.w;
            }
            bbs[tid] = 1.7159f * fast_tanh(0.666f * (a0 + a1));
        }
        __syncthreads();
        // phase 1: 4 head projections (ff1/ff2 tanh'd; ta/tb linear)
        {
            float a0 = hbs[tid], a1 = 0.f, a2 = 0.f, a3 = 0.f;
            const float4* w4 = (const float4*)&whead[tid * 132];
            const float4* b4 = (const float4*)bbs;
#pragma unroll
            for (int k4 = 0; k4 < 32; k4 += 4) {
                float4 wv = w4[k4], bv = b4[k4];
                a0 += wv.x * bv.x + wv.y * bv.y + wv.z * bv.z + wv.w * bv.w;
                float4 wv1 = w4[k4 + 1], bv1 = b4[k4 + 1];
                a1 += wv1.x * bv1.x + wv1.y * bv1.y + wv1.z * bv1.z + wv1.w * bv1.w;
                float4 wv2 = w4[k4 + 2], bv2 = b4[k4 + 2];
                a2 += wv2.x * bv2.x + wv2.y * bv2.y + wv2.z * bv2.z + wv2.w * bv2.w;
                float4 wv3 = w4[k4 + 3], bv3 = b4[k4 + 3];
                a3 += wv3.x * bv3.x + wv3.y * bv3.y + wv3.z * bv3.z + wv3.w * bv3.w;
            }
            float acc = (a0 + a1) + (a2 + a3);
            if (tid < 128) acc = fast_tanh(acc);
            heads[tid] = acc;
        }
        __syncthreads();
        // phase 2: gated interpolation
        if (tid < 64) {
            float ti = fast_sig(heads[128 + tid] + heads[192 + tid]);
            float hn = heads[tid] * (1.f - ti) + ti * heads[64 + tid];
            hs[tid] = hn;
            outs[ts * 68 + tid] = hn;
        }
        __syncthreads();
    }

    // logits epilogue
    for (int t = tid; t < 512; t += 256) {
        int s = t >> 3, o = t & 7;
        float a0 = obs[o], a1 = 0.f;
        const float* r = &outs[s * 68];
        const float* wv = &outw[o * 68];
#pragma unroll
        for (int i = 0; i < 64; i += 2) {
            a0 += r[i] * wv[i];
            a1 += r[i + 1] * wv[i + 1];
        }
        out[(size_t)(b * TT + s) * 8 + o] = a0 + a1;
    }
    if (out_size >= 18432 && tid < 64) out[16384 + b * 64 + tid] = hs[tid];
}

// ---------------------------------------------------------------------------
extern "C" void kernel_launch(void* const* d_in, const int* in_sizes, int n_in,
                              void* d_out, int out_size) {
    const float* x_vis   = (const float*)d_in[0];
    const float* hx      = (const float*)d_in[1];
    const float* conv1_w = (const float*)d_in[2];
    const float* conv1_b = (const float*)d_in[3];
    const float* conv2_w = (const float*)d_in[4];
    const float* conv2_b = (const float*)d_in[5];
    const float* bb_w    = (const float*)d_in[6];
    const float* bb_b    = (const float*)d_in[7];
    const float* ff1_w   = (const float*)d_in[8];
    const float* ff1_b   = (const float*)d_in[9];
    const float* ff2_w   = (const float*)d_in[10];
    const float* ff2_b   = (const float*)d_in[11];
    const float* ta_w    = (const float*)d_in[12];
    const float* ta_b    = (const float*)d_in[13];
    const float* tb_w    = (const float*)d_in[14];
    const float* tb_b    = (const float*)d_in[15];
    const float* out_w   = (const float*)d_in[16];
    const float* out_b   = (const float*)d_in[17];
    float* out = (float*)d_out;

    const size_t smf = (size_t)SMF_FLOATS * sizeof(float);   // ~205.6 KB
    const size_t smr = (size_t)48232 * sizeof(float);        // ~192.9 KB

    cudaFuncSetAttribute(fused_conv_kernel, cudaFuncAttributeMaxDynamicSharedMemorySize, (int)smf);
    cudaFuncSetAttribute(recur_kernel, cudaFuncAttributeMaxDynamicSharedMemorySize, (int)smr);

    prep_kernel<<<128, 256>>>(conv1_w, conv2_w);
    fused_conv_kernel<<<NT, 512, smf>>>(x_vis, conv1_b, conv2_b);
    gemm_pre_kernel<<<dim3(16, KSPLIT), 256>>>(bb_w);
    reduce_kernel<<<256, 256>>>();
    recur_kernel<<<BB, 256, smr>>>(hx, bb_w, bb_b,
                                   ff1_w, ff1_b, ff2_w, ff2_b,
                                   ta_w, ta_b, tb_w, tb_b,
                                   out_w, out_b, out, out_size);
}

// round 5
// speedup vs baseline: 7.2718x; 1.3980x over previous
#include <cuda_runtime.h>
#include <cuda_fp16.h>
#include <math.h>

#define BB 32
#define TT 64
#define NT 2048        // BB*TT images
#define KSPLIT 8

// Scratch (static device globals — allocation-free kernel_launch)
__device__ __half g_feats[(size_t)NT * 16384];        // conv2 out fp16: [n][oc*256+p]
__device__ float  g_prep[(size_t)KSPLIT * NT * 128];  // split-K partials (fp32)
__device__ float  g_prepr[(size_t)NT * 128];          // reduced partials
__device__ uint4  g_w1f[192];                          // conv1 B-fragments (3 ks x 2 ntp x 32)
__device__ uint4  g_w2f[4096];                         // conv2 B-fragments (32 ks x 4 ntp x 32)
__device__ uint4  g_bwf[262144];                       // bb_w B-fragments (1024 ks x 8 ntp x 32)

// ---------------------------------------------------------------------------
// helpers
// ---------------------------------------------------------------------------
__device__ __forceinline__ unsigned h2pack(float lo, float hi) {
    __half2 h = __floats2half2_rn(lo, hi);
    return *(unsigned*)&h;
}

#define MMA_F16(d, a0, a1, a2, a3, b0, b1)                                    \
    asm volatile("mma.sync.aligned.m16n8k16.row.col.f32.f16.f16.f32 "         \
                 "{%0,%1,%2,%3}, {%4,%5,%6,%7}, {%8,%9}, {%0,%1,%2,%3};"      \
                 : "+f"(d[0]), "+f"(d[1]), "+f"(d[2]), "+f"(d[3])             \
                 : "r"(a0), "r"(a1), "r"(a2), "r"(a3), "r"(b0), "r"(b1))

__device__ __forceinline__ float fast_tanh(float x) {
    float e = __expf(2.f * x);
    return 1.f - __fdividef(2.f, e + 1.f);
}
__device__ __forceinline__ float fast_sig(float x) {
    return __fdividef(1.f, 1.f + __expf(-x));
}

// ---------------------------------------------------------------------------
// prep: pack all B operands into m16n8k16 fragment layout (fp16)
// blocks 0..1023: bbw kstep tiles (smem transpose). block 1024: w2. block 1025: w1.
// ---------------------------------------------------------------------------
__global__ void prep_kernel(const float* __restrict__ w1, const float* __restrict__ w2,
                            const float* __restrict__ bbw) {
    const int blk = blockIdx.x, t = threadIdx.x;
    if (blk < 1024) {
        __shared__ float sm[2048];            // 16 k-rows x 128 n
        const float4* src = (const float4*)(bbw + (size_t)blk * 16 * 128);
        for (int i = t; i < 512; i += 256) ((float4*)sm)[i] = src[i];   // FIXED: full 512 float4
        __syncthreads();
        int ntp = t >> 5, lane = t & 31;
        int tig = lane & 3, gid = lane >> 2;
        int c = tig * 2, n = ntp * 16 + gid;
        uint4 v;
        v.x = h2pack(sm[c * 128 + n],           sm[(c + 1) * 128 + n]);
        v.y = h2pack(sm[(c + 8) * 128 + n],     sm[(c + 9) * 128 + n]);
        v.z = h2pack(sm[c * 128 + n + 8],       sm[(c + 1) * 128 + n + 8]);
        v.w = h2pack(sm[(c + 8) * 128 + n + 8], sm[(c + 9) * 128 + n + 8]);
        g_bwf[blk * 256 + t] = v;
    } else if (blk == 1024) {
        for (int j = 0; j < 16; j++) {
            int idx = t + j * 256;            // 4096 total
            int ks = idx >> 7, ntp = (idx >> 5) & 3, lane = idx & 31;
            int tig = lane & 3, gid = lane >> 2;
            int c = ks * 16 + tig * 2, n = ntp * 16 + gid;
            uint4 v;
            v.x = h2pack(w2[n * 512 + c],           w2[n * 512 + c + 1]);
            v.y = h2pack(w2[n * 512 + c + 8],       w2[n * 512 + c + 9]);
            v.z = h2pack(w2[(n + 8) * 512 + c],     w2[(n + 8) * 512 + c + 1]);
            v.w = h2pack(w2[(n + 8) * 512 + c + 8], w2[(n + 8) * 512 + c + 9]);
            g_w2f[idx] = v;
        }
    } else {
        if (t < 192) {
            int ks = t >> 6, ntp = (t >> 5) & 1, lane = t & 31;
            int tig = lane & 3, gid = lane >> 2;
            int c = ks * 16 + tig * 2, n = ntp * 16 + gid;
            uint4 v;
            v.x = h2pack(w1[n * 48 + c],           w1[n * 48 + c + 1]);
            v.y = h2pack(w1[n * 48 + c + 8],       w1[n * 48 + c + 9]);
            v.z = h2pack(w1[(n + 8) * 48 + c],     w1[(n + 8) * 48 + c + 1]);
            v.w = h2pack(w1[(n + 8) * 48 + c + 8], w1[(n + 8) * 48 + c + 9]);
            g_w1f[t] = v;
        }
    }
}

// ---------------------------------------------------------------------------
// Fused conv1+conv2 per image, fp16 m16n8k16. One CTA per image, 512 threads.
// SMEM bytes: act[32*1156 h]=73984 | x[3*4356 h]=26144 | w2f=65536 | w1f=3072 |
//             p2t=2048 | p1t=192 | bi1=128 | bi2=256   total 171360
// ---------------------------------------------------------------------------
#define CB_ACT 0
#define CB_X   73984
#define CB_W2  100128
#define CB_W1  165664
#define CB_P2  168736
#define CB_P1  170784
#define CB_BI1 170976
#define CB_BI2 171104
#define CB_TOT 171360

__global__ __launch_bounds__(512, 1) void fused_conv_kernel(
    const float* __restrict__ x_vis,
    const float* __restrict__ b1g, const float* __restrict__ b2g) {
    extern __shared__ char smc[];
    __half* act_s = (__half*)(smc + CB_ACT);
    __half* xs    = (__half*)(smc + CB_X);
    uint4*  w2f   = (uint4*)(smc + CB_W2);
    uint4*  w1f   = (uint4*)(smc + CB_W1);
    int*    p2t   = (int*)(smc + CB_P2);
    int*    p1t   = (int*)(smc + CB_P1);
    float*  bi1   = (float*)(smc + CB_BI1);
    float*  bi2   = (float*)(smc + CB_BI2);

    const int n = blockIdx.x, tid = threadIdx.x;
    const int lane = tid & 31, w = tid >> 5;
    const int tig = lane & 3, gid = lane >> 2;

    // zero act + x regions (6258 uint4)
    {
        uint4 z = make_uint4(0, 0, 0, 0);
        uint4* zp = (uint4*)smc;
        for (int t = tid; t < 6258; t += 512) zp[t] = z;
    }
    if (tid < 48)  p1t[tid] = (tid >> 4) * 4356 + ((tid >> 2) & 3) * 66 + (tid & 3);
    if (tid < 512) p2t[tid] = (tid >> 4) * 1156 + ((tid >> 2) & 3) * 34 + (tid & 3);
    if (tid < 192) w1f[tid] = g_w1f[tid];
    for (int t = tid; t < 4096; t += 512) w2f[t] = g_w2f[t];
    if (tid < 32) bi1[tid] = b1g[tid];
    if (tid < 64) bi2[tid] = b2g[tid];
    __syncthreads();

    // load x -> fp16 padded smem
    const float* xg = x_vis + (size_t)n * 12288;
    for (int t = tid; t < 12288; t += 512) {
        int ic = t >> 12, r = t & 4095, y = r >> 6, xx = r & 63;
        xs[ic * 4356 + (y + 1) * 66 + xx + 1] = __float2half_rn(xg[t]);
    }
    __syncthreads();

    // ---- conv1: M=1024, N=32, K=48 (3 k16-steps) ----
    {
        float acc1[4][4][4];
#pragma unroll
        for (int a = 0; a < 4; a++)
#pragma unroll
            for (int b = 0; b < 4; b++)
#pragma unroll
                for (int c = 0; c < 4; c++) acc1[a][b][c] = 0.f;
        int pbl[4], pbh[4];
#pragma unroll
        for (int mt = 0; mt < 4; mt++) {
            int pl = w * 64 + mt * 16 + gid, ph = pl + 8;
            pbl[mt] = ((pl >> 5) * 2) * 66 + (pl & 31) * 2;
            pbh[mt] = ((ph >> 5) * 2) * 66 + (ph & 31) * 2;
        }
#pragma unroll
        for (int ks = 0; ks < 3; ks++) {
            uint4 bv0 = w1f[(ks * 2 + 0) * 32 + lane];
            uint4 bv1 = w1f[(ks * 2 + 1) * 32 + lane];
            int c0 = ks * 16 + tig * 2;
            int o0 = p1t[c0], o1 = p1t[c0 + 8];
#pragma unroll
            for (int mt = 0; mt < 4; mt++) {
                unsigned a0 = *(const unsigned*)&xs[o0 + pbl[mt]];
                unsigned a1 = *(const unsigned*)&xs[o0 + pbh[mt]];
                unsigned a2 = *(const unsigned*)&xs[o1 + pbl[mt]];
                unsigned a3 = *(const unsigned*)&xs[o1 + pbh[mt]];
                MMA_F16(acc1[mt][0], a0, a1, a2, a3, bv0.x, bv0.y);
                MMA_F16(acc1[mt][1], a0, a1, a2, a3, bv0.z, bv0.w);
                MMA_F16(acc1[mt][2], a0, a1, a2, a3, bv1.x, bv1.y);
                MMA_F16(acc1[mt][3], a0, a1, a2, a3, bv1.z, bv1.w);
            }
        }
        __syncthreads();   // x reads complete before act epilogue ordering below
        // epilogue: relu+bias -> fp16 padded act smem [oc][y+1][x+1]
#pragma unroll
        for (int mt = 0; mt < 4; mt++) {
            int pl = w * 64 + mt * 16 + gid, ph = pl + 8;
            int yl = ((pl >> 5) + 1) * 34 + (pl & 31) + 1;
            int yh = ((ph >> 5) + 1) * 34 + (ph & 31) + 1;
#pragma unroll
            for (int nt = 0; nt < 4; nt++) {
                int oc = nt * 8 + 2 * tig;
                act_s[oc * 1156 + yl]       = __float2half_rn(fmaxf(acc1[mt][nt][0] + bi1[oc], 0.f));
                act_s[(oc + 1) * 1156 + yl] = __float2half_rn(fmaxf(acc1[mt][nt][1] + bi1[oc + 1], 0.f));
                act_s[oc * 1156 + yh]       = __float2half_rn(fmaxf(acc1[mt][nt][2] + bi1[oc], 0.f));
                act_s[(oc + 1) * 1156 + yh] = __float2half_rn(fmaxf(acc1[mt][nt][3] + bi1[oc + 1], 0.f));
            }
        }
    }
    __syncthreads();

    // ---- conv2: M=256, N=64, K=512 (32 k16-steps) ----
    {
        float acc2[8][4];
#pragma unroll
        for (int a = 0; a < 8; a++)
#pragma unroll
            for (int c = 0; c < 4; c++) acc2[a][c] = 0.f;
        const int pl = w * 16 + gid, ph = pl + 8;
        const int pbl = ((pl >> 4) * 2) * 34 + (pl & 15) * 2;
        const int pbh = ((ph >> 4) * 2) * 34 + (ph & 15) * 2;

#pragma unroll 4
        for (int s = 0; s < 32; s++) {
            int c0 = s * 16 + tig * 2;
            int o0 = p2t[c0], o1 = p2t[c0 + 8];
            unsigned a0 = *(const unsigned*)&act_s[o0 + pbl];
            unsigned a1 = *(const unsigned*)&act_s[o0 + pbh];
            unsigned a2 = *(const unsigned*)&act_s[o1 + pbl];
            unsigned a3 = *(const unsigned*)&act_s[o1 + pbh];
            uint4 b0v = w2f[(s * 4 + 0) * 32 + lane];
            uint4 b1v = w2f[(s * 4 + 1) * 32 + lane];
            uint4 b2v = w2f[(s * 4 + 2) * 32 + lane];
            uint4 b3v = w2f[(s * 4 + 3) * 32 + lane];
            MMA_F16(acc2[0], a0, a1, a2, a3, b0v.x, b0v.y);
            MMA_F16(acc2[1], a0, a1, a2, a3, b0v.z, b0v.w);
            MMA_F16(acc2[2], a0, a1, a2, a3, b1v.x, b1v.y);
            MMA_F16(acc2[3], a0, a1, a2, a3, b1v.z, b1v.w);
            MMA_F16(acc2[4], a0, a1, a2, a3, b2v.x, b2v.y);
            MMA_F16(acc2[5], a0, a1, a2, a3, b2v.z, b2v.w);
            MMA_F16(acc2[6], a0, a1, a2, a3, b3v.x, b3v.y);
            MMA_F16(acc2[7], a0, a1, a2, a3, b3v.z, b3v.w);
        }
        // epilogue -> g_feats fp16
        __half* fo = g_feats + (size_t)n * 16384;
#pragma unroll
        for (int nt = 0; nt < 8; nt++) {
            int oc = nt * 8 + 2 * tig;
            fo[oc * 256 + pl]       = __float2half_rn(fmaxf(acc2[nt][0] + bi2[oc], 0.f));
            fo[(oc + 1) * 256 + pl] = __float2half_rn(fmaxf(acc2[nt][1] + bi2[oc + 1], 0.f));
            fo[oc * 256 + ph]       = __float2half_rn(fmaxf(acc2[nt][2] + bi2[oc], 0.f));
            fo[(oc + 1) * 256 + ph] = __float2half_rn(fmaxf(acc2[nt][3] + bi2[oc + 1], 0.f));
        }
    }
}

// ---------------------------------------------------------------------------
// fp16 GEMM: g_prep[s] = feats(2048 x 2048-chunk) @ bbw-chunk (128 cols).
// Grid (16 M-tiles of 128, KSPLIT), 256 threads, reg-prefetch double buffering.
// ---------------------------------------------------------------------------
__global__ __launch_bounds__(256, 1) void gemm_pre_kernel() {
    __shared__ __half As[128 * 40];
    __shared__ uint4  Bs[512];
    const int tid = threadIdx.x, lane = tid & 31, w = tid >> 5;
    const int tig = lane & 3, gid = lane >> 2;
    const int m0 = blockIdx.x * 128;
    const int kb = blockIdx.y * 2048;
    const int arow = tid >> 1, acol = (tid & 1) * 16;

    float acc[16][4];
#pragma unroll
    for (int a = 0; a < 16; a++)
#pragma unroll
        for (int c = 0; c < 4; c++) acc[a][c] = 0.f;

    uint4 pa0, pa1, pb0, pb1;
#define G_LD(kt)                                                               \
    {                                                                          \
        const __half* ap = &g_feats[(size_t)(m0 + arow) * 16384 + kb + (kt) + acol]; \
        pa0 = *(const uint4*)ap;                                               \
        pa1 = *(const uint4*)(ap + 8);                                         \
        const uint4* bp = &g_bwf[((size_t)(kb + (kt)) >> 4) * 256 + tid];      \
        pb0 = bp[0];                                                           \
        pb1 = bp[256];                                                         \
    }
#define G_ST()                                                                 \
    {                                                                          \
        *(uint4*)&As[arow * 40 + acol] = pa0;                                  \
        *(uint4*)&As[arow * 40 + acol + 8] = pa1;                              \
        Bs[tid] = pb0;                                                         \
        Bs[tid + 256] = pb1;                                                   \
    }

    G_LD(0);
    G_ST();
    __syncthreads();

    for (int it = 0; it < 64; it++) {
        if (it < 63) G_LD((it + 1) * 32);
#pragma unroll
        for (int ks2 = 0; ks2 < 2; ks2++) {
            const __half* ap = &As[(w * 16 + gid) * 40 + ks2 * 16 + tig * 2];
            unsigned a0 = *(const unsigned*)ap;
            unsigned a1 = *(const unsigned*)(ap + 8 * 40);
            unsigned a2 = *(const unsigned*)(ap + 8);
            unsigned a3 = *(const unsigned*)(ap + 8 * 40 + 8);
#pragma unroll
            for (int ntp = 0; ntp < 8; ntp++) {
                uint4 bv = Bs[ks2 * 256 + ntp * 32 + lane];
                MMA_F16(acc[ntp * 2], a0, a1, a2, a3, bv.x, bv.y);
                MMA_F16(acc[ntp * 2 + 1], a0, a1, a2, a3, bv.z, bv.w);
            }
        }
        __syncthreads();
        if (it < 63) {
            G_ST();
            __syncthreads();
        }
    }

    float* op = g_prep + (size_t)blockIdx.y * (NT * 128);
    const int r0 = m0 + w * 16 + gid;
#pragma unroll
    for (int nt = 0; nt < 16; nt++) {
        *(float2*)&op[(size_t)r0 * 128 + nt * 8 + 2 * tig] = make_float2(acc[nt][0], acc[nt][1]);
        *(float2*)&op[(size_t)(r0 + 8) * 128 + nt * 8 + 2 * tig] = make_float2(acc[nt][2], acc[nt][3]);
    }
}

// ---------------------------------------------------------------------------
// reduce split-K partials: g_prepr = sum_s g_prep[s]
// ---------------------------------------------------------------------------
__global__ void reduce_kernel() {
    int i = blockIdx.x * 256 + threadIdx.x;   // over 65536 float4
    const float4* src = (const float4*)g_prep;
    float4 a = src[i];
#pragma unroll
    for (int s = 1; s < KSPLIT; s++) {
        float4 b = src[(size_t)s * 65536 + i];
        a.x += b.x; a.y += b.y; a.z += b.z; a.w += b.w;
    }
    ((float4*)g_prepr)[i] = a;
}

// ---------------------------------------------------------------------------
// CfC recurrent scan + logits. One CTA per batch element, weights in SMEM.
// ---------------------------------------------------------------------------
__global__ void recur_kernel(const float* __restrict__ hx,
                             const float* __restrict__ bbw,
                             const float* __restrict__ bbb,
                             const float* __restrict__ f1w, const float* __restrict__ f1b,
                             const float* __restrict__ f2w, const float* __restrict__ f2b,
                             const float* __restrict__ taw, const float* __restrict__ tab,
                             const float* __restrict__ tbw, const float* __restrict__ tbb,
                             const float* __restrict__ ow,  const float* __restrict__ ob,
                             float* __restrict__ out, int out_size) {
    extern __shared__ float sm[];
    float* wh    = sm;                  // [128][68]
    float* whead = wh + 128 * 68;       // [256][132]
    float* outw  = whead + 256 * 132;   // [8][68]
    float* bbbs  = outw + 8 * 68;       // [128]
    float* hbs   = bbbs + 128;          // [256]
    float* obs   = hbs + 256;           // [8]
    float* hs    = obs + 8;             // [64]
    float* bbs   = hs + 64;             // [128]
    float* heads = bbs + 128;           // [256]
    float* outs  = heads + 256;         // [64][68]
    const int b = blockIdx.x, tid = threadIdx.x;

    for (int t = tid; t < 128 * 64; t += 256) {
        int j = t >> 6, k = t & 63;
        wh[j * 68 + k] = bbw[(size_t)(16384 + k) * 128 + j];
    }
    for (int t = tid; t < 4 * 64 * 128; t += 256) {
        int m = t >> 13, r = t & 8191, i = r >> 7, k = r & 127;
        const float* W = (m == 0) ? f1w : (m == 1) ? f2w : (m == 2) ? taw : tbw;
        whead[(m * 64 + i) * 132 + k] = W[k * 64 + i];
    }
    for (int t = tid; t < 512; t += 256) {
        int i = t >> 3, o = t & 7;
        outw[o * 68 + i] = ow[t];
    }
    if (tid < 128) bbbs[tid] = bbb[tid];
    {
        int m = tid >> 6, i = tid & 63;
        hbs[tid] = (m == 0) ? f1b[i] : (m == 1) ? f2b[i] : (m == 2) ? tab[i] : tbb[i];
    }
    if (tid < 8)  obs[tid] = ob[tid];
    if (tid < 64) hs[tid] = hx[b * 64 + tid];
    __syncthreads();

    float nxt = (tid < 128) ? g_prepr[(size_t)(b * TT) * 128 + tid] : 0.f;

    for (int ts = 0; ts < TT; ts++) {
        float cur = nxt;
        if (ts < TT - 1 && tid < 128)
            nxt = g_prepr[(size_t)(b * TT + ts + 1) * 128 + tid];
        if (tid < 128) {
            float a0 = bbbs[tid] + cur, a1 = 0.f;
            const float4* w4 = (const float4*)&wh[tid * 68];
            const float4* h4 = (const float4*)hs;
#pragma unroll
            for (int k4 = 0; k4 < 16; k4 += 2) {
                float4 wv = w4[k4], hv = h4[k4];
                a0 += wv.x * hv.x + wv.y * hv.y + wv.z * hv.z + wv.w * hv.w;
                float4 wv2 = w4[k4 + 1], hv2 = h4[k4 + 1];
                a1 += wv2.x * hv2.x + wv2.y * hv2.y + wv2.z * hv2.z + wv2.w * hv2.w;
            }
            bbs[tid] = 1.7159f * fast_tanh(0.666f * (a0 + a1));
        }
        __syncthreads();
        {
            float a0 = hbs[tid], a1 = 0.f, a2 = 0.f, a3 = 0.f;
            const float4* w4 = (const float4*)&whead[tid * 132];
            const float4* b4 = (const float4*)bbs;
#pragma unroll
            for (int k4 = 0; k4 < 32; k4 += 4) {
                float4 wv = w4[k4], bv = b4[k4];
                a0 += wv.x * bv.x + wv.y * bv.y + wv.z * bv.z + wv.w * bv.w;
                float4 wv1 = w4[k4 + 1], bv1 = b4[k4 + 1];
                a1 += wv1.x * bv1.x + wv1.y * bv1.y + wv1.z * bv1.z + wv1.w * bv1.w;
                float4 wv2 = w4[k4 + 2], bv2 = b4[k4 + 2];
                a2 += wv2.x * bv2.x + wv2.y * bv2.y + wv2.z * bv2.z + wv2.w * bv2.w;
                float4 wv3 = w4[k4 + 3], bv3 = b4[k4 + 3];
                a3 += wv3.x * bv3.x + wv3.y * bv3.y + wv3.z * bv3.z + wv3.w * bv3.w;
            }
            float acc = (a0 + a1) + (a2 + a3);
            if (tid < 128) acc = fast_tanh(acc);
            heads[tid] = acc;
        }
        __syncthreads();
        if (tid < 64) {
            float ti = fast_sig(heads[128 + tid] + heads[192 + tid]);
            float hn = heads[tid] * (1.f - ti) + ti * heads[64 + tid];
            hs[tid] = hn;
            outs[ts * 68 + tid] = hn;
        }
        __syncthreads();
    }

    for (int t = tid; t < 512; t += 256) {
        int s = t >> 3, o = t & 7;
        float a0 = obs[o], a1 = 0.f;
        const float* r = &outs[s * 68];
        const float* wv = &outw[o * 68];
#pragma unroll
        for (int i = 0; i < 64; i += 2) {
            a0 += r[i] * wv[i];
            a1 += r[i + 1] * wv[i + 1];
        }
        out[(size_t)(b * TT + s) * 8 + o] = a0 + a1;
    }
    if (out_size >= 18432 && tid < 64) out[16384 + b * 64 + tid] = hs[tid];
}

// ---------------------------------------------------------------------------
extern "C" void kernel_launch(void* const* d_in, const int* in_sizes, int n_in,
                              void* d_out, int out_size) {
    const float* x_vis   = (const float*)d_in[0];
    const float* hx      = (const float*)d_in[1];
    const float* conv1_w = (const float*)d_in[2];
    const float* conv1_b = (const float*)d_in[3];
    const float* conv2_w = (const float*)d_in[4];
    const float* conv2_b = (const float*)d_in[5];
    const float* bb_w    = (const float*)d_in[6];
    const float* bb_b    = (const float*)d_in[7];
    const float* ff1_w   = (const float*)d_in[8];
    const float* ff1_b   = (const float*)d_in[9];
    const float* ff2_w   = (const float*)d_in[10];
    const float* ff2_b   = (const float*)d_in[11];
    const float* ta_w    = (const float*)d_in[12];
    const float* ta_b    = (const float*)d_in[13];
    const float* tb_w    = (const float*)d_in[14];
    const float* tb_b    = (const float*)d_in[15];
    const float* out_w   = (const float*)d_in[16];
    const float* out_b   = (const float*)d_in[17];
    float* out = (float*)d_out;

    const size_t smf = CB_TOT;                             // 171360 B
    const size_t smr = (size_t)48232 * sizeof(float);      // ~192.9 KB

    cudaFuncSetAttribute(fused_conv_kernel, cudaFuncAttributeMaxDynamicSharedMemorySize, (int)smf);
    cudaFuncSetAttribute(recur_kernel, cudaFuncAttributeMaxDynamicSharedMemorySize, (int)smr);

    prep_kernel<<<1026, 256>>>(conv1_w, conv2_w, bb_w);
    fused_conv_kernel<<<NT, 512, smf>>>(x_vis, conv1_b, conv2_b);
    gemm_pre_kernel<<<dim3(16, KSPLIT), 256>>>();
    reduce_kernel<<<256, 256>>>();
    recur_kernel<<<BB, 256, smr>>>(hx, bb_w, bb_b,
                                   ff1_w, ff1_b, ff2_w, ff2_b,
                                   ta_w, ta_b, tb_w, tb_b,
                                   out_w, out_b, out, out_size);
}

// round 7
// speedup vs baseline: 8.7167x; 1.1987x over previous
#include <cuda_runtime.h>
#include <cuda_fp16.h>
#include <math.h>

#define BB 32
#define TT 64
#define NT 2048        // BB*TT images
#define KSPLIT 16

// Scratch (static device globals — allocation-free kernel_launch)
__device__ __half g_feats[(size_t)NT * 16384];        // conv2 out fp16: [n][oc*256+p]
__device__ float  g_prep[(size_t)KSPLIT * NT * 128];  // split-K partials (fp32)
__device__ float  g_prepr[(size_t)NT * 128];          // reduced partials
__device__ uint4  g_w1f[192];                          // conv1 B-fragments (3 ks x 2 ntp x 32)
__device__ uint4  g_w2f[4096];                         // conv2 B-fragments (32 ks x 4 ntp x 32)
__device__ uint4  g_bwf[262144];                       // bb_w B-fragments (1024 ks x 8 ntp x 32)

// ---------------------------------------------------------------------------
// helpers
// ---------------------------------------------------------------------------
__device__ __forceinline__ unsigned h2pack(float lo, float hi) {
    __half2 h = __floats2half2_rn(lo, hi);
    return *(unsigned*)&h;
}

#define MMA_F16(d, a0, a1, a2, a3, b0, b1)                                    \
    asm volatile("mma.sync.aligned.m16n8k16.row.col.f32.f16.f16.f32 "         \
                 "{%0,%1,%2,%3}, {%4,%5,%6,%7}, {%8,%9}, {%0,%1,%2,%3};"      \
                 : "+f"(d[0]), "+f"(d[1]), "+f"(d[2]), "+f"(d[3])             \
                 : "r"(a0), "r"(a1), "r"(a2), "r"(a3), "r"(b0), "r"(b1))

__device__ __forceinline__ float fast_tanh(float x) {
    float e = __expf(2.f * x);
    return 1.f - __fdividef(2.f, e + 1.f);
}
__device__ __forceinline__ float fast_sig(float x) {
    return __fdividef(1.f, 1.f + __expf(-x));
}

// ---------------------------------------------------------------------------
// prep: pack all B operands into m16n8k16 fragment layout (fp16)
// blocks 0..1023: bbw kstep tiles (smem transpose). block 1024: w2. block 1025: w1.
// ---------------------------------------------------------------------------
__global__ void prep_kernel(const float* __restrict__ w1, const float* __restrict__ w2,
                            const float* __restrict__ bbw) {
    const int blk = blockIdx.x, t = threadIdx.x;
    if (blk < 1024) {
        __shared__ float sm[2048];            // 16 k-rows x 128 n
        const float4* src = (const float4*)(bbw + (size_t)blk * 16 * 128);
        for (int i = t; i < 512; i += 256) ((float4*)sm)[i] = src[i];
        __syncthreads();
        int ntp = t >> 5, lane = t & 31;
        int tig = lane & 3, gid = lane >> 2;
        int c = tig * 2, n = ntp * 16 + gid;
        uint4 v;
        v.x = h2pack(sm[c * 128 + n],           sm[(c + 1) * 128 + n]);
        v.y = h2pack(sm[(c + 8) * 128 + n],     sm[(c + 9) * 128 + n]);
        v.z = h2pack(sm[c * 128 + n + 8],       sm[(c + 1) * 128 + n + 8]);
        v.w = h2pack(sm[(c + 8) * 128 + n + 8], sm[(c + 9) * 128 + n + 8]);
        g_bwf[blk * 256 + t] = v;
    } else if (blk == 1024) {
        for (int j = 0; j < 16; j++) {
            int idx = t + j * 256;            // 4096 total
            int ks = idx >> 7, ntp = (idx >> 5) & 3, lane = idx & 31;
            int tig = lane & 3, gid = lane >> 2;
            int c = ks * 16 + tig * 2, n = ntp * 16 + gid;
            uint4 v;
            v.x = h2pack(w2[n * 512 + c],           w2[n * 512 + c + 1]);
            v.y = h2pack(w2[n * 512 + c + 8],       w2[n * 512 + c + 9]);
            v.z = h2pack(w2[(n + 8) * 512 + c],     w2[(n + 8) * 512 + c + 1]);
            v.w = h2pack(w2[(n + 8) * 512 + c + 8], w2[(n + 8) * 512 + c + 9]);
            g_w2f[idx] = v;
        }
    } else {
        if (t < 192) {
            int ks = t >> 6, ntp = (t >> 5) & 1, lane = t & 31;
            int tig = lane & 3, gid = lane >> 2;
            int c = ks * 16 + tig * 2, n = ntp * 16 + gid;
            uint4 v;
            v.x = h2pack(w1[n * 48 + c],           w1[n * 48 + c + 1]);
            v.y = h2pack(w1[n * 48 + c + 8],       w1[n * 48 + c + 9]);
            v.z = h2pack(w1[(n + 8) * 48 + c],     w1[(n + 8) * 48 + c + 1]);
            v.w = h2pack(w1[(n + 8) * 48 + c + 8], w1[(n + 8) * 48 + c + 9]);
            g_w1f[t] = v;
        }
    }
}

// ---------------------------------------------------------------------------
// Fused conv1+conv2 per image, fp16 m16n8k16. One CTA per image, 512 threads.
// Occupancy 2: w2 B-fragments are read straight from gmem (L1/L2-resident).
// SMEM bytes: act[32*1156 h]=73984 | x[3*4356 h]=26144 | w1f=3072 |
//             p2t=2048 | p1t=192 | bi1=128 | bi2=256   total 105824
// ---------------------------------------------------------------------------
#define CB_ACT 0
#define CB_X   73984
#define CB_W1  100128
#define CB_P2  103200
#define CB_P1  105248
#define CB_BI1 105440
#define CB_BI2 105568
#define CB_TOT 105824

__global__ __launch_bounds__(512, 2) void fused_conv_kernel(
    const float* __restrict__ x_vis,
    const float* __restrict__ b1g, const float* __restrict__ b2g) {
    extern __shared__ char smc[];
    __half* act_s = (__half*)(smc + CB_ACT);
    __half* xs    = (__half*)(smc + CB_X);
    uint4*  w1f   = (uint4*)(smc + CB_W1);
    int*    p2t   = (int*)(smc + CB_P2);
    int*    p1t   = (int*)(smc + CB_P1);
    float*  bi1   = (float*)(smc + CB_BI1);
    float*  bi2   = (float*)(smc + CB_BI2);

    const int n = blockIdx.x, tid = threadIdx.x;
    const int lane = tid & 31, w = tid >> 5;
    const int tig = lane & 3, gid = lane >> 2;

    // zero act + x regions (6258 uint4)
    {
        uint4 z = make_uint4(0, 0, 0, 0);
        uint4* zp = (uint4*)smc;
        for (int t = tid; t < 6258; t += 512) zp[t] = z;
    }
    if (tid < 48)  p1t[tid] = (tid >> 4) * 4356 + ((tid >> 2) & 3) * 66 + (tid & 3);
    if (tid < 512) p2t[tid] = (tid >> 4) * 1156 + ((tid >> 2) & 3) * 34 + (tid & 3);
    if (tid < 192) w1f[tid] = g_w1f[tid];
    if (tid < 32) bi1[tid] = b1g[tid];
    if (tid < 64) bi2[tid] = b2g[tid];
    __syncthreads();

    // load x -> fp16 padded smem
    const float* xg = x_vis + (size_t)n * 12288;
    for (int t = tid; t < 12288; t += 512) {
        int ic = t >> 12, r = t & 4095, y = r >> 6, xx = r & 63;
        xs[ic * 4356 + (y + 1) * 66 + xx + 1] = __float2half_rn(xg[t]);
    }
    __syncthreads();

    // ---- conv1: M=1024, N=32, K=48 (3 k16-steps), two M-passes for regs ----
#pragma unroll
    for (int half = 0; half < 2; half++) {
        float acc1[2][4][4];
#pragma unroll
        for (int a = 0; a < 2; a++)
#pragma unroll
            for (int b = 0; b < 4; b++)
#pragma unroll
                for (int c = 0; c < 4; c++) acc1[a][b][c] = 0.f;
        int pbl[2], pbh[2];
#pragma unroll
        for (int mt = 0; mt < 2; mt++) {
            int pl = w * 64 + (half * 2 + mt) * 16 + gid, ph = pl + 8;
            pbl[mt] = ((pl >> 5) * 2) * 66 + (pl & 31) * 2;
            pbh[mt] = ((ph >> 5) * 2) * 66 + (ph & 31) * 2;
        }
#pragma unroll
        for (int ks = 0; ks < 3; ks++) {
            uint4 bv0 = w1f[(ks * 2 + 0) * 32 + lane];
            uint4 bv1 = w1f[(ks * 2 + 1) * 32 + lane];
            int c0 = ks * 16 + tig * 2;
            int o0 = p1t[c0], o1 = p1t[c0 + 8];
#pragma unroll
            for (int mt = 0; mt < 2; mt++) {
                unsigned a0 = *(const unsigned*)&xs[o0 + pbl[mt]];
                unsigned a1 = *(const unsigned*)&xs[o0 + pbh[mt]];
                unsigned a2 = *(const unsigned*)&xs[o1 + pbl[mt]];
                unsigned a3 = *(const unsigned*)&xs[o1 + pbh[mt]];
                MMA_F16(acc1[mt][0], a0, a1, a2, a3, bv0.x, bv0.y);
                MMA_F16(acc1[mt][1], a0, a1, a2, a3, bv0.z, bv0.w);
                MMA_F16(acc1[mt][2], a0, a1, a2, a3, bv1.x, bv1.y);
                MMA_F16(acc1[mt][3], a0, a1, a2, a3, bv1.z, bv1.w);
            }
        }
        // epilogue: relu+bias -> fp16 padded act smem [oc][y+1][x+1]
        // (no sync needed: conv1 never reads act_s; barrier before conv2 covers it)
#pragma unroll
        for (int mt = 0; mt < 2; mt++) {
            int pl = w * 64 + (half * 2 + mt) * 16 + gid, ph = pl + 8;
            int yl = ((pl >> 5) + 1) * 34 + (pl & 31) + 1;
            int yh = ((ph >> 5) + 1) * 34 + (ph & 31) + 1;
#pragma unroll
            for (int nt = 0; nt < 4; nt++) {
                int oc = nt * 8 + 2 * tig;
                act_s[oc * 1156 + yl]       = __float2half_rn(fmaxf(acc1[mt][nt][0] + bi1[oc], 0.f));
                act_s[(oc + 1) * 1156 + yl] = __float2half_rn(fmaxf(acc1[mt][nt][1] + bi1[oc + 1], 0.f));
                act_s[oc * 1156 + yh]       = __float2half_rn(fmaxf(acc1[mt][nt][2] + bi1[oc], 0.f));
                act_s[(oc + 1) * 1156 + yh] = __float2half_rn(fmaxf(acc1[mt][nt][3] + bi1[oc + 1], 0.f));
            }
        }
    }
    __syncthreads();

    // ---- conv2: M=256, N=64, K=512 (32 k16-steps), B fragments from gmem ----
    {
        float acc2[8][4];
#pragma unroll
        for (int a = 0; a < 8; a++)
#pragma unroll
            for (int c = 0; c < 4; c++) acc2[a][c] = 0.f;
        const int pl = w * 16 + gid, ph = pl + 8;
        const int pbl = ((pl >> 4) * 2) * 34 + (pl & 15) * 2;
        const int pbh = ((ph >> 4) * 2) * 34 + (ph & 15) * 2;

#pragma unroll 2
        for (int s = 0; s < 32; s++) {
            int c0 = s * 16 + tig * 2;
            int o0 = p2t[c0], o1 = p2t[c0 + 8];
            const uint4* bp = &g_w2f[s * 128 + lane];
            uint4 b0v = bp[0];
            uint4 b1v = bp[32];
            uint4 b2v = bp[64];
            uint4 b3v = bp[96];
            unsigned a0 = *(const unsigned*)&act_s[o0 + pbl];
            unsigned a1 = *(const unsigned*)&act_s[o0 + pbh];
            unsigned a2 = *(const unsigned*)&act_s[o1 + pbl];
            unsigned a3 = *(const unsigned*)&act_s[o1 + pbh];
            MMA_F16(acc2[0], a0, a1, a2, a3, b0v.x, b0v.y);
            MMA_F16(acc2[1], a0, a1, a2, a3, b0v.z, b0v.w);
            MMA_F16(acc2[2], a0, a1, a2, a3, b1v.x, b1v.y);
            MMA_F16(acc2[3], a0, a1, a2, a3, b1v.z, b1v.w);
            MMA_F16(acc2[4], a0, a1, a2, a3, b2v.x, b2v.y);
            MMA_F16(acc2[5], a0, a1, a2, a3, b2v.z, b2v.w);
            MMA_F16(acc2[6], a0, a1, a2, a3, b3v.x, b3v.y);
            MMA_F16(acc2[7], a0, a1, a2, a3, b3v.z, b3v.w);
        }
        // epilogue -> g_feats fp16
        __half* fo = g_feats + (size_t)n * 16384;
#pragma unroll
        for (int nt = 0; nt < 8; nt++) {
            int oc = nt * 8 + 2 * tig;
            fo[oc * 256 + pl]       = __float2half_rn(fmaxf(acc2[nt][0] + bi2[oc], 0.f));
            fo[(oc + 1) * 256 + pl] = __float2half_rn(fmaxf(acc2[nt][1] + bi2[oc + 1], 0.f));
            fo[oc * 256 + ph]       = __float2half_rn(fmaxf(acc2[nt][2] + bi2[oc], 0.f));
            fo[(oc + 1) * 256 + ph] = __float2half_rn(fmaxf(acc2[nt][3] + bi2[oc + 1], 0.f));
        }
    }
}

// ---------------------------------------------------------------------------
// fp16 GEMM: g_prep[s] = feats(2048 x 1024-chunk) @ bbw-chunk (128 cols).
// Grid (16 M-tiles of 128, KSPLIT=16), 256 threads, reg-prefetch double buffer.
// ---------------------------------------------------------------------------
__global__ __launch_bounds__(256, 2) void gemm_pre_kernel() {
    __shared__ __half As[128 * 40];
    __shared__ uint4  Bs[512];
    const int tid = threadIdx.x, lane = tid & 31, w = tid >> 5;
    const int tig = lane & 3, gid = lane >> 2;
    const int m0 = blockIdx.x * 128;
    const int kb = blockIdx.y * 1024;
    const int arow = tid >> 1, acol = (tid & 1) * 16;

    float acc[16][4];
#pragma unroll
    for (int a = 0; a < 16; a++)
#pragma unroll
        for (int c = 0; c < 4; c++) acc[a][c] = 0.f;

    uint4 pa0, pa1, pb0, pb1;
#define G_LD(kt)                                                               \
    {                                                                          \
        const __half* ap = &g_feats[(size_t)(m0 + arow) * 16384 + kb + (kt) + acol]; \
        pa0 = *(const uint4*)ap;                                               \
        pa1 = *(const uint4*)(ap + 8);                                         \
        const uint4* bp = &g_bwf[((size_t)(kb + (kt)) >> 4) * 256 + tid];      \
        pb0 = bp[0];                                                           \
        pb1 = bp[256];                                                         \
    }
#define G_ST()                                                                 \
    {                                                                          \
        *(uint4*)&As[arow * 40 + acol] = pa0;                                  \
        *(uint4*)&As[arow * 40 + acol + 8] = pa1;                              \
        Bs[tid] = pb0;                                                         \
        Bs[tid + 256] = pb1;                                                   \
    }

    G_LD(0);
    G_ST();
    __syncthreads();

    for (int it = 0; it < 32; it++) {
        if (it < 31) G_LD((it + 1) * 32);
#pragma unroll
        for (int ks2 = 0; ks2 < 2; ks2++) {
            const __half* ap = &As[(w * 16 + gid) * 40 + ks2 * 16 + tig * 2];
            unsigned a0 = *(const unsigned*)ap;
            unsigned a1 = *(const unsigned*)(ap + 8 * 40);
            unsigned a2 = *(const unsigned*)(ap + 8);
            unsigned a3 = *(const unsigned*)(ap + 8 * 40 + 8);
#pragma unroll
            for (int ntp = 0; ntp < 8; ntp++) {
                uint4 bv = Bs[ks2 * 256 + ntp * 32 + lane];
                MMA_F16(acc[ntp * 2], a0, a1, a2, a3, bv.x, bv.y);
                MMA_F16(acc[ntp * 2 + 1], a0, a1, a2, a3, bv.z, bv.w);
            }
        }
        __syncthreads();
        if (it < 31) {
            G_ST();
            __syncthreads();
        }
    }

    float* op = g_prep + (size_t)blockIdx.y * (NT * 128);
    const int r0 = m0 + w * 16 + gid;
#pragma unroll
    for (int nt = 0; nt < 16; nt++) {
        *(float2*)&op[(size_t)r0 * 128 + nt * 8 + 2 * tig] = make_float2(acc[nt][0], acc[nt][1]);
        *(float2*)&op[(size_t)(r0 + 8) * 128 + nt * 8 + 2 * tig] = make_float2(acc[nt][2], acc[nt][3]);
    }
}

// ---------------------------------------------------------------------------
// reduce split-K partials: g_prepr = sum_s g_prep[s]
// ---------------------------------------------------------------------------
__global__ void reduce_kernel() {
    int i = blockIdx.x * 256 + threadIdx.x;   // over 65536 float4
    const float4* src = (const float4*)g_prep;
    float4 a = src[i];
#pragma unroll
    for (int s = 1; s < KSPLIT; s++) {
        float4 b = src[(size_t)s * 65536 + i];
        a.x += b.x; a.y += b.y; a.z += b.z; a.w += b.w;
    }
    ((float4*)g_prepr)[i] = a;
}

// ---------------------------------------------------------------------------
// CfC recurrent scan + logits. One CTA per batch element, weights in SMEM.
// Gate heads merged: sigmoid(ta+tb) = sigmoid((ta_w+tb_w)@bb + ta_b+tb_b).
// ---------------------------------------------------------------------------
__global__ void recur_kernel(const float* __restrict__ hx,
                             const float* __restrict__ bbw,
                             const float* __restrict__ bbb,
                             const float* __restrict__ f1w, const float* __restrict__ f1b,
                             const float* __restrict__ f2w, const float* __restrict__ f2b,
                             const float* __restrict__ taw, const float* __restrict__ tab,
                             const float* __restrict__ tbw, const float* __restrict__ tbb,
                             const float* __restrict__ ow,  const float* __restrict__ ob,
                             float* __restrict__ out, int out_size) {
    extern __shared__ float sm[];
    float* wh    = sm;                  // [128][68]
    float* whead = wh + 128 * 68;       // [192][132]  (ff1 | ff2 | ta+tb)
    float* outw  = whead + 192 * 132;   // [8][68]
    float* bbbs  = outw + 8 * 68;       // [128]
    float* hbs   = bbbs + 128;          // [192]
    float* obs   = hbs + 192;           // [8]
    float* hs    = obs + 8;             // [64]
    float* bbs   = hs + 64;             // [128]
    float* heads = bbs + 128;           // [192]
    float* outs  = heads + 192;         // [64][68]
    const int b = blockIdx.x, tid = threadIdx.x;

    for (int t = tid; t < 128 * 64; t += 256) {
        int j = t >> 6, k = t & 63;
        wh[j * 68 + k] = bbw[(size_t)(16384 + k) * 128 + j];
    }
    for (int t = tid; t < 3 * 64 * 128; t += 256) {
        int m = t >> 13, r = t & 8191, i = r >> 7, k = r & 127;
        float v = (m == 0) ? f1w[k * 64 + i] : (m == 1) ? f2w[k * 64 + i]
                                             : (taw[k * 64 + i] + tbw[k * 64 + i]);
        whead[(m * 64 + i) * 132 + k] = v;
    }
    for (int t = tid; t < 512; t += 256) {
        int i = t >> 3, o = t & 7;
        outw[o * 68 + i] = ow[t];
    }
    if (tid < 128) bbbs[tid] = bbb[tid];
    if (tid < 192) {
        int m = tid >> 6, i = tid & 63;
        hbs[tid] = (m == 0) ? f1b[i] : (m == 1) ? f2b[i] : (tab[i] + tbb[i]);
    }
    if (tid < 8)  obs[tid] = ob[tid];
    if (tid < 64) hs[tid] = hx[b * 64 + tid];
    __syncthreads();

    float nxt = (tid < 128) ? g_prepr[(size_t)(b * TT) * 128 + tid] : 0.f;

    for (int ts = 0; ts < TT; ts++) {
        float cur = nxt;
        if (ts < TT - 1 && tid < 128)
            nxt = g_prepr[(size_t)(b * TT + ts + 1) * 128 + tid];
        if (tid < 128) {
            float a0 = bbbs[tid] + cur, a1 = 0.f;
            const float4* w4 = (const float4*)&wh[tid * 68];
            const float4* h4 = (const float4*)hs;
#pragma unroll
            for (int k4 = 0; k4 < 16; k4 += 2) {
                float4 wv = w4[k4], hv = h4[k4];
                a0 += wv.x * hv.x + wv.y * hv.y + wv.z * hv.z + wv.w * hv.w;
                float4 wv2 = w4[k4 + 1], hv2 = h4[k4 + 1];
                a1 += wv2.x * hv2.x + wv2.y * hv2.y + wv2.z * hv2.z + wv2.w * hv2.w;
            }
            bbs[tid] = 1.7159f * fast_tanh(0.666f * (a0 + a1));
        }
        __syncthreads();
        if (tid < 192) {
            float a0 = hbs[tid], a1 = 0.f, a2 = 0.f, a3 = 0.f;
            const float4* w4 = (const float4*)&whead[tid * 132];
            const float4* b4 = (const float4*)bbs;
#pragma unroll
            for (int k4 = 0; k4 < 32; k4 += 4) {
                float4 wv = w4[k4], bv = b4[k4];
                a0 += wv.x * bv.x + wv.y * bv.y + wv.z * bv.z + wv.w * bv.w;
                float4 wv1 = w4[k4 + 1], bv1 = b4[k4 + 1];
                a1 += wv1.x * bv1.x + wv1.y * bv1.y + wv1.z * bv1.z + wv1.w * bv1.w;
                float4 wv2 = w4[k4 + 2], bv2 = b4[k4 + 2];
                a2 += wv2.x * bv2.x + wv2.y * bv2.y + wv2.z * bv2.z + wv2.w * bv2.w;
                float4 wv3 = w4[k4 + 3], bv3 = b4[k4 + 3];
                a3 += wv3.x * bv3.x + wv3.y * bv3.y + wv3.z * bv3.z + wv3.w * bv3.w;
            }
            float acc = (a0 + a1) + (a2 + a3);
            if (tid < 128) acc = fast_tanh(acc);
            heads[tid] = acc;
        }
        __syncthreads();
        if (tid < 64) {
            float ti = fast_sig(heads[128 + tid]);
            float hn = heads[tid] * (1.f - ti) + ti * heads[64 + tid];
            hs[tid] = hn;
            outs[ts * 68 + tid] = hn;
        }
        __syncthreads();
    }

    for (int t = tid; t < 512; t += 256) {
        int s = t >> 3, o = t & 7;
        float a0 = obs[o], a1 = 0.f;
        const float* r = &outs[s * 68];
        const float* wv = &outw[o * 68];
#pragma unroll
        for (int i = 0; i < 64; i += 2) {
            a0 += r[i] * wv[i];
            a1 += r[i + 1] * wv[i + 1];
        }
        out[(size_t)(b * TT + s) * 8 + o] = a0 + a1;
    }
    if (out_size >= 18432 && tid < 64) out[16384 + b * 64 + tid] = hs[tid];
}

// ---------------------------------------------------------------------------
extern "C" void kernel_launch(void* const* d_in, const int* in_sizes, int n_in,
                              void* d_out, int out_size) {
    const float* x_vis   = (const float*)d_in[0];
    const float* hx      = (const float*)d_in[1];
    const float* conv1_w = (const float*)d_in[2];
    const float* conv1_b = (const float*)d_in[3];
    const float* conv2_w = (const float*)d_in[4];
    const float* conv2_b = (const float*)d_in[5];
    const float* bb_w    = (const float*)d_in[6];
    const float* bb_b    = (const float*)d_in[7];
    const float* ff1_w   = (const float*)d_in[8];
    const float* ff1_b   = (const float*)d_in[9];
    const float* ff2_w   = (const float*)d_in[10];
    const float* ff2_b   = (const float*)d_in[11];
    const float* ta_w    = (const float*)d_in[12];
    const float* ta_b    = (const float*)d_in[13];
    const float* tb_w    = (const float*)d_in[14];
    const float* tb_b    = (const float*)d_in[15];
    const float* out_w   = (const float*)d_in[16];
    const float* out_b   = (const float*)d_in[17];
    float* out = (float*)d_out;

    const size_t smf = CB_TOT;                             // 105824 B (occ 2)
    const size_t smr = (size_t)(128*68 + 192*132 + 8*68 + 128 + 192 + 8 + 64 + 128 + 192 + 64*68)
                       * sizeof(float);                    // ~158.7 KB

    cudaFuncSetAttribute(fused_conv_kernel, cudaFuncAttributeMaxDynamicSharedMemorySize, (int)smf);
    cudaFuncSetAttribute(recur_kernel, cudaFuncAttributeMaxDynamicSharedMemorySize, (int)smr);

    prep_kernel<<<1026, 256>>>(conv1_w, conv2_w, bb_w);
    fused_conv_kernel<<<NT, 512, smf>>>(x_vis, conv1_b, conv2_b);
    gemm_pre_kernel<<<dim3(16, KSPLIT), 256>>>();
    reduce_kernel<<<256, 256>>>();
    recur_kernel<<<BB, 256, smr>>>(hx, bb_w, bb_b,
                                   ff1_w, ff1_b, ff2_w, ff2_b,
                                   ta_w, ta_b, tb_w, tb_b,
                                   out_w, out_b, out, out_size);
}

// round 8
// speedup vs baseline: 9.4157x; 1.0802x over previous
#include <cuda_runtime.h>
#include <cuda_fp16.h>
#include <math.h>

#define BB 32
#define TT 64
#define NT 2048        // BB*TT images
#define KSPLIT 16

// Scratch (static device globals — allocation-free kernel_launch)
__device__ __half g_feats[(size_t)NT * 16384];        // conv2 out fp16: [n][oc*256+p]
__device__ float  g_prep[(size_t)KSPLIT * NT * 128];  // split-K partials (fp32)
__device__ float  g_prepr[(size_t)NT * 128];          // reduced partials
__device__ uint4  g_w1f[192];                          // conv1 B-fragments (3 ks x 2 ntp x 32)
__device__ uint4  g_w2f[4096];                         // conv2 B-fragments (32 ks x 4 ntp x 32)
__device__ uint4  g_bwf[262144];                       // bb_w B-fragments (1024 ks x 8 ntp x 32)

// ---------------------------------------------------------------------------
// helpers
// ---------------------------------------------------------------------------
__device__ __forceinline__ unsigned h2pack(float lo, float hi) {
    __half2 h = __floats2half2_rn(lo, hi);
    return *(unsigned*)&h;
}

#define MMA_F16(d, a0, a1, a2, a3, b0, b1)                                    \
    asm volatile("mma.sync.aligned.m16n8k16.row.col.f32.f16.f16.f32 "         \
                 "{%0,%1,%2,%3}, {%4,%5,%6,%7}, {%8,%9}, {%0,%1,%2,%3};"      \
                 : "+f"(d[0]), "+f"(d[1]), "+f"(d[2]), "+f"(d[3])             \
                 : "r"(a0), "r"(a1), "r"(a2), "r"(a3), "r"(b0), "r"(b1))

__device__ __forceinline__ float fast_tanh(float x) {
    float e = __expf(2.f * x);
    return 1.f - __fdividef(2.f, e + 1.f);
}
__device__ __forceinline__ float fast_sig(float x) {
    return __fdividef(1.f, 1.f + __expf(-x));
}

// ---------------------------------------------------------------------------
// prep: pack all B operands into m16n8k16 fragment layout (fp16)
// blocks 0..1023: bbw kstep tiles (smem transpose). block 1024: w2. block 1025: w1.
// ---------------------------------------------------------------------------
__global__ void prep_kernel(const float* __restrict__ w1, const float* __restrict__ w2,
                            const float* __restrict__ bbw) {
    const int blk = blockIdx.x, t = threadIdx.x;
    if (blk < 1024) {
        __shared__ float sm[2048];            // 16 k-rows x 128 n
        const float4* src = (const float4*)(bbw + (size_t)blk * 16 * 128);
        for (int i = t; i < 512; i += 256) ((float4*)sm)[i] = src[i];
        __syncthreads();
        int ntp = t >> 5, lane = t & 31;
        int tig = lane & 3, gid = lane >> 2;
        int c = tig * 2, n = ntp * 16 + gid;
        uint4 v;
        v.x = h2pack(sm[c * 128 + n],           sm[(c + 1) * 128 + n]);
        v.y = h2pack(sm[(c + 8) * 128 + n],     sm[(c + 9) * 128 + n]);
        v.z = h2pack(sm[c * 128 + n + 8],       sm[(c + 1) * 128 + n + 8]);
        v.w = h2pack(sm[(c + 8) * 128 + n + 8], sm[(c + 9) * 128 + n + 8]);
        g_bwf[blk * 256 + t] = v;
    } else if (blk == 1024) {
        for (int j = 0; j < 16; j++) {
            int idx = t + j * 256;            // 4096 total
            int ks = idx >> 7, ntp = (idx >> 5) & 3, lane = idx & 31;
            int tig = lane & 3, gid = lane >> 2;
            int c = ks * 16 + tig * 2, n = ntp * 16 + gid;
            uint4 v;
            v.x = h2pack(w2[n * 512 + c],           w2[n * 512 + c + 1]);
            v.y = h2pack(w2[n * 512 + c + 8],       w2[n * 512 + c + 9]);
            v.z = h2pack(w2[(n + 8) * 512 + c],     w2[(n + 8) * 512 + c + 1]);
            v.w = h2pack(w2[(n + 8) * 512 + c + 8], w2[(n + 8) * 512 + c + 9]);
            g_w2f[idx] = v;
        }
    } else {
        if (t < 192) {
            int ks = t >> 6, ntp = (t >> 5) & 1, lane = t & 31;
            int tig = lane & 3, gid = lane >> 2;
            int c = ks * 16 + tig * 2, n = ntp * 16 + gid;
            uint4 v;
            v.x = h2pack(w1[n * 48 + c],           w1[n * 48 + c + 1]);
            v.y = h2pack(w1[n * 48 + c + 8],       w1[n * 48 + c + 9]);
            v.z = h2pack(w1[(n + 8) * 48 + c],     w1[(n + 8) * 48 + c + 1]);
            v.w = h2pack(w1[(n + 8) * 48 + c + 8], w1[(n + 8) * 48 + c + 9]);
            g_w1f[t] = v;
        }
    }
}

// ---------------------------------------------------------------------------
// Fused conv1+conv2 per image, fp16 m16n8k16. One CTA per image, 512 threads.
// Occupancy 2: w2 B-fragments are read straight from gmem (L1/L2-resident).
// SMEM bytes: act[32*1156 h]=73984 | x[3*4356 h]=26144 | w1f=3072 |
//             p2t=2048 | p1t=192 | bi1=128 | bi2=256   total 105824
// ---------------------------------------------------------------------------
#define CB_ACT 0
#define CB_X   73984
#define CB_W1  100128
#define CB_P2  103200
#define CB_P1  105248
#define CB_BI1 105440
#define CB_BI2 105568
#define CB_TOT 105824

__global__ __launch_bounds__(512, 2) void fused_conv_kernel(
    const float* __restrict__ x_vis,
    const float* __restrict__ b1g, const float* __restrict__ b2g) {
    extern __shared__ char smc[];
    __half* act_s = (__half*)(smc + CB_ACT);
    __half* xs    = (__half*)(smc + CB_X);
    uint4*  w1f   = (uint4*)(smc + CB_W1);
    int*    p2t   = (int*)(smc + CB_P2);
    int*    p1t   = (int*)(smc + CB_P1);
    float*  bi1   = (float*)(smc + CB_BI1);
    float*  bi2   = (float*)(smc + CB_BI2);

    const int n = blockIdx.x, tid = threadIdx.x;
    const int lane = tid & 31, w = tid >> 5;
    const int tig = lane & 3, gid = lane >> 2;

    // zero act + x regions (6258 uint4)
    {
        uint4 z = make_uint4(0, 0, 0, 0);
        uint4* zp = (uint4*)smc;
        for (int t = tid; t < 6258; t += 512) zp[t] = z;
    }
    if (tid < 48)  p1t[tid] = (tid >> 4) * 4356 + ((tid >> 2) & 3) * 66 + (tid & 3);
    if (tid < 512) p2t[tid] = (tid >> 4) * 1156 + ((tid >> 2) & 3) * 34 + (tid & 3);
    if (tid < 192) w1f[tid] = g_w1f[tid];
    if (tid < 32) bi1[tid] = b1g[tid];
    if (tid < 64) bi2[tid] = b2g[tid];
    __syncthreads();

    // load x -> fp16 padded smem
    const float* xg = x_vis + (size_t)n * 12288;
    for (int t = tid; t < 12288; t += 512) {
        int ic = t >> 12, r = t & 4095, y = r >> 6, xx = r & 63;
        xs[ic * 4356 + (y + 1) * 66 + xx + 1] = __float2half_rn(xg[t]);
    }
    __syncthreads();

    // ---- conv1: M=1024, N=32, K=48 (3 k16-steps), two M-passes for regs ----
#pragma unroll
    for (int half = 0; half < 2; half++) {
        float acc1[2][4][4];
#pragma unroll
        for (int a = 0; a < 2; a++)
#pragma unroll
            for (int b = 0; b < 4; b++)
#pragma unroll
                for (int c = 0; c < 4; c++) acc1[a][b][c] = 0.f;
        int pbl[2], pbh[2];
#pragma unroll
        for (int mt = 0; mt < 2; mt++) {
            int pl = w * 64 + (half * 2 + mt) * 16 + gid, ph = pl + 8;
            pbl[mt] = ((pl >> 5) * 2) * 66 + (pl & 31) * 2;
            pbh[mt] = ((ph >> 5) * 2) * 66 + (ph & 31) * 2;
        }
#pragma unroll
        for (int ks = 0; ks < 3; ks++) {
            uint4 bv0 = w1f[(ks * 2 + 0) * 32 + lane];
            uint4 bv1 = w1f[(ks * 2 + 1) * 32 + lane];
            int c0 = ks * 16 + tig * 2;
            int o0 = p1t[c0], o1 = p1t[c0 + 8];
#pragma unroll
            for (int mt = 0; mt < 2; mt++) {
                unsigned a0 = *(const unsigned*)&xs[o0 + pbl[mt]];
                unsigned a1 = *(const unsigned*)&xs[o0 + pbh[mt]];
                unsigned a2 = *(const unsigned*)&xs[o1 + pbl[mt]];
                unsigned a3 = *(const unsigned*)&xs[o1 + pbh[mt]];
                MMA_F16(acc1[mt][0], a0, a1, a2, a3, bv0.x, bv0.y);
                MMA_F16(acc1[mt][1], a0, a1, a2, a3, bv0.z, bv0.w);
                MMA_F16(acc1[mt][2], a0, a1, a2, a3, bv1.x, bv1.y);
                MMA_F16(acc1[mt][3], a0, a1, a2, a3, bv1.z, bv1.w);
            }
        }
        // epilogue: relu+bias -> fp16 padded act smem [oc][y+1][x+1]
        // (no sync needed: conv1 never reads act_s; barrier before conv2 covers it)
#pragma unroll
        for (int mt = 0; mt < 2; mt++) {
            int pl = w * 64 + (half * 2 + mt) * 16 + gid, ph = pl + 8;
            int yl = ((pl >> 5) + 1) * 34 + (pl & 31) + 1;
            int yh = ((ph >> 5) + 1) * 34 + (ph & 31) + 1;
#pragma unroll
            for (int nt = 0; nt < 4; nt++) {
                int oc = nt * 8 + 2 * tig;
                act_s[oc * 1156 + yl]       = __float2half_rn(fmaxf(acc1[mt][nt][0] + bi1[oc], 0.f));
                act_s[(oc + 1) * 1156 + yl] = __float2half_rn(fmaxf(acc1[mt][nt][1] + bi1[oc + 1], 0.f));
                act_s[oc * 1156 + yh]       = __float2half_rn(fmaxf(acc1[mt][nt][2] + bi1[oc], 0.f));
                act_s[(oc + 1) * 1156 + yh] = __float2half_rn(fmaxf(acc1[mt][nt][3] + bi1[oc + 1], 0.f));
            }
        }
    }
    __syncthreads();

    // ---- conv2: M=256, N=64, K=512 (32 k16-steps), B fragments from gmem ----
    {
        float acc2[8][4];
#pragma unroll
        for (int a = 0; a < 8; a++)
#pragma unroll
            for (int c = 0; c < 4; c++) acc2[a][c] = 0.f;
        const int pl = w * 16 + gid, ph = pl + 8;
        const int pbl = ((pl >> 4) * 2) * 34 + (pl & 15) * 2;
        const int pbh = ((ph >> 4) * 2) * 34 + (ph & 15) * 2;

#pragma unroll 2
        for (int s = 0; s < 32; s++) {
            int c0 = s * 16 + tig * 2;
            int o0 = p2t[c0], o1 = p2t[c0 + 8];
            const uint4* bp = &g_w2f[s * 128 + lane];
            uint4 b0v = bp[0];
            uint4 b1v = bp[32];
            uint4 b2v = bp[64];
            uint4 b3v = bp[96];
            unsigned a0 = *(const unsigned*)&act_s[o0 + pbl];
            unsigned a1 = *(const unsigned*)&act_s[o0 + pbh];
            unsigned a2 = *(const unsigned*)&act_s[o1 + pbl];
            unsigned a3 = *(const unsigned*)&act_s[o1 + pbh];
            MMA_F16(acc2[0], a0, a1, a2, a3, b0v.x, b0v.y);
            MMA_F16(acc2[1], a0, a1, a2, a3, b0v.z, b0v.w);
            MMA_F16(acc2[2], a0, a1, a2, a3, b1v.x, b1v.y);
            MMA_F16(acc2[3], a0, a1, a2, a3, b1v.z, b1v.w);
            MMA_F16(acc2[4], a0, a1, a2, a3, b2v.x, b2v.y);
            MMA_F16(acc2[5], a0, a1, a2, a3, b2v.z, b2v.w);
            MMA_F16(acc2[6], a0, a1, a2, a3, b3v.x, b3v.y);
            MMA_F16(acc2[7], a0, a1, a2, a3, b3v.z, b3v.w);
        }
        // epilogue -> g_feats fp16
        __half* fo = g_feats + (size_t)n * 16384;
#pragma unroll
        for (int nt = 0; nt < 8; nt++) {
            int oc = nt * 8 + 2 * tig;
            fo[oc * 256 + pl]       = __float2half_rn(fmaxf(acc2[nt][0] + bi2[oc], 0.f));
            fo[(oc + 1) * 256 + pl] = __float2half_rn(fmaxf(acc2[nt][1] + bi2[oc + 1], 0.f));
            fo[oc * 256 + ph]       = __float2half_rn(fmaxf(acc2[nt][2] + bi2[oc], 0.f));
            fo[(oc + 1) * 256 + ph] = __float2half_rn(fmaxf(acc2[nt][3] + bi2[oc + 1], 0.f));
        }
    }
}

// ---------------------------------------------------------------------------
// fp16 GEMM: g_prep[s] = feats(2048 x 1024-chunk) @ bbw-chunk (128 cols).
// Grid (16 M-tiles of 128, KSPLIT=16), 256 threads, reg-prefetch double buffer.
// ---------------------------------------------------------------------------
__global__ __launch_bounds__(256, 2) void gemm_pre_kernel() {
    __shared__ __half As[128 * 40];
    __shared__ uint4  Bs[512];
    const int tid = threadIdx.x, lane = tid & 31, w = tid >> 5;
    const int tig = lane & 3, gid = lane >> 2;
    const int m0 = blockIdx.x * 128;
    const int kb = blockIdx.y * 1024;
    const int arow = tid >> 1, acol = (tid & 1) * 16;

    float acc[16][4];
#pragma unroll
    for (int a = 0; a < 16; a++)
#pragma unroll
        for (int c = 0; c < 4; c++) acc[a][c] = 0.f;

    uint4 pa0, pa1, pb0, pb1;
#define G_LD(kt)                                                               \
    {                                                                          \
        const __half* ap = &g_feats[(size_t)(m0 + arow) * 16384 + kb + (kt) + acol]; \
        pa0 = *(const uint4*)ap;                                               \
        pa1 = *(const uint4*)(ap + 8);                                         \
        const uint4* bp = &g_bwf[((size_t)(kb + (kt)) >> 4) * 256 + tid];      \
        pb0 = bp[0];                                                           \
        pb1 = bp[256];                                                         \
    }
#define G_ST()                                                                 \
    {                                                                          \
        *(uint4*)&As[arow * 40 + acol] = pa0;                                  \
        *(uint4*)&As[arow * 40 + acol + 8] = pa1;                              \
        Bs[tid] = pb0;                                                         \
        Bs[tid + 256] = pb1;                                                   \
    }

    G_LD(0);
    G_ST();
    __syncthreads();

    for (int it = 0; it < 32; it++) {
        if (it < 31) G_LD((it + 1) * 32);
#pragma unroll
        for (int ks2 = 0; ks2 < 2; ks2++) {
            const __half* ap = &As[(w * 16 + gid) * 40 + ks2 * 16 + tig * 2];
            unsigned a0 = *(const unsigned*)ap;
            unsigned a1 = *(const unsigned*)(ap + 8 * 40);
            unsigned a2 = *(const unsigned*)(ap + 8);
            unsigned a3 = *(const unsigned*)(ap + 8 * 40 + 8);
#pragma unroll
            for (int ntp = 0; ntp < 8; ntp++) {
                uint4 bv = Bs[ks2 * 256 + ntp * 32 + lane];
                MMA_F16(acc[ntp * 2], a0, a1, a2, a3, bv.x, bv.y);
                MMA_F16(acc[ntp * 2 + 1], a0, a1, a2, a3, bv.z, bv.w);
            }
        }
        __syncthreads();
        if (it < 31) {
            G_ST();
            __syncthreads();
        }
    }

    float* op = g_prep + (size_t)blockIdx.y * (NT * 128);
    const int r0 = m0 + w * 16 + gid;
#pragma unroll
    for (int nt = 0; nt < 16; nt++) {
        *(float2*)&op[(size_t)r0 * 128 + nt * 8 + 2 * tig] = make_float2(acc[nt][0], acc[nt][1]);
        *(float2*)&op[(size_t)(r0 + 8) * 128 + nt * 8 + 2 * tig] = make_float2(acc[nt][2], acc[nt][3]);
    }
}

// ---------------------------------------------------------------------------
// reduce split-K partials: g_prepr = sum_s g_prep[s]
// ---------------------------------------------------------------------------
__global__ void reduce_kernel() {
    int i = blockIdx.x * 256 + threadIdx.x;   // over 65536 float4
    const float4* src = (const float4*)g_prep;
    float4 a = src[i];
#pragma unroll
    for (int s = 1; s < KSPLIT; s++) {
        float4 b = src[(size_t)s * 65536 + i];
        a.x += b.x; a.y += b.y; a.z += b.z; a.w += b.w;
    }
    ((float4*)g_prepr)[i] = a;
}

// ---------------------------------------------------------------------------
// CfC recurrent scan + logits. One CTA per batch, 512 threads,
// REGISTER-RESIDENT weights (no per-step smem weight traffic).
//   phase0: 4 threads/output (16 K each) + shfl_xor(1,2)
//   phase1: 2 threads/output (64 K each) + shfl_xor(1)
// Gate heads merged: sigmoid((ta_w+tb_w)@bb + ta_b+tb_b).
// ---------------------------------------------------------------------------
__global__ __launch_bounds__(512, 1) void recur_kernel(
                             const float* __restrict__ hx,
                             const float* __restrict__ bbw,
                             const float* __restrict__ bbb,
                             const float* __restrict__ f1w, const float* __restrict__ f1b,
                             const float* __restrict__ f2w, const float* __restrict__ f2b,
                             const float* __restrict__ taw, const float* __restrict__ tab,
                             const float* __restrict__ tbw, const float* __restrict__ tbb,
                             const float* __restrict__ ow,  const float* __restrict__ ob,
                             float* __restrict__ out, int out_size) {
    __shared__ float hs[64];
    __shared__ float bbs[128];
    __shared__ float heads[192];
    __shared__ float outs[64 * 68];
    __shared__ float outw[8 * 68];
    __shared__ float obs[8];
    const int b = blockIdx.x, tid = threadIdx.x;

    // phase0 ownership: output j0 (0..127), K-part p0 (0..3) of 16
    const int j0 = tid >> 2, p0 = tid & 3;
    float w0[16];
#pragma unroll
    for (int kk = 0; kk < 16; kk++)
        w0[kk] = bbw[(size_t)(16384 + p0 * 16 + kk) * 128 + j0];
    const float bias0 = bbb[j0];

    // phase1 ownership: output j1 (0..191), K-part p1 (0..1) of 64
    const int j1 = tid >> 1, p1 = tid & 1;
    const int m = (tid < 384) ? (j1 >> 6) : 0;
    const int i = j1 & 63;
    float w1r[64];
    float bias1 = 0.f;
    if (tid < 384) {
        if (m == 2) {
#pragma unroll 8
            for (int kk = 0; kk < 64; kk++) {
                int k = p1 * 64 + kk;
                w1r[kk] = taw[k * 64 + i] + tbw[k * 64 + i];
            }
            bias1 = tab[i] + tbb[i];
        } else {
            const float* Wm = (m == 1) ? f2w : f1w;
#pragma unroll 8
            for (int kk = 0; kk < 64; kk++)
                w1r[kk] = Wm[(p1 * 64 + kk) * 64 + i];
            bias1 = (m == 1) ? f2b[i] : f1b[i];
        }
    }

    if (tid < 512) {
        int s = tid >> 3, o = tid & 7;
        outw[o * 68 + s] = ow[s * 8 + o];
    }
    if (tid < 8)  obs[tid] = ob[tid];
    if (tid < 64) hs[tid] = hx[b * 64 + tid];
    __syncthreads();

    float nxt = (p0 == 0) ? g_prepr[(size_t)(b * TT) * 128 + j0] : 0.f;

    for (int ts = 0; ts < TT; ts++) {
        float cur = nxt;
        if (ts < TT - 1 && p0 == 0)
            nxt = g_prepr[(size_t)(b * TT + ts + 1) * 128 + j0];
        // phase 0: bb = lecun_tanh(pre + h @ Wh), 4 lanes per output
        {
            float a0 = 0.f, a1 = 0.f;
            const float4* h4 = (const float4*)(hs + p0 * 16);
#pragma unroll
            for (int q = 0; q < 4; q++) {
                float4 hv = h4[q];
                a0 += w0[q * 4 + 0] * hv.x + w0[q * 4 + 1] * hv.y;
                a1 += w0[q * 4 + 2] * hv.z + w0[q * 4 + 3] * hv.w;
            }
            float d = a0 + a1;
            d += __shfl_xor_sync(0xffffffffu, d, 1);
            d += __shfl_xor_sync(0xffffffffu, d, 2);
            if (p0 == 0)
                bbs[j0] = 1.7159f * fast_tanh(0.666f * (d + bias0 + cur));
        }
        __syncthreads();
        // phase 1: heads (ff1/ff2 tanh'd; merged gate linear), 2 lanes per output
        if (tid < 384) {
            float a0 = 0.f, a1 = 0.f, a2 = 0.f, a3 = 0.f;
            const float4* b4 = (const float4*)(bbs + p1 * 64);
#pragma unroll
            for (int q = 0; q < 16; q += 2) {
                float4 bv = b4[q];
                a0 += w1r[q * 4 + 0] * bv.x + w1r[q * 4 + 1] * bv.y;
                a1 += w1r[q * 4 + 2] * bv.z + w1r[q * 4 + 3] * bv.w;
                float4 bv2 = b4[q + 1];
                a2 += w1r[q * 4 + 4] * bv2.x + w1r[q * 4 + 5] * bv2.y;
                a3 += w1r[q * 4 + 6] * bv2.z + w1r[q * 4 + 7] * bv2.w;
            }
            float d = (a0 + a1) + (a2 + a3);
            d += __shfl_xor_sync(0xffffffffu, d, 1);
            if (p1 == 0) {
                d += bias1;
                heads[j1] = (m < 2) ? fast_tanh(d) : d;
            }
        }
        __syncthreads();
        // phase 2: gated interpolation
        if (tid < 64) {
            float ti = fast_sig(heads[128 + tid]);
            float hn = heads[tid] * (1.f - ti) + ti * heads[64 + tid];
            hs[tid] = hn;
            outs[ts * 68 + tid] = hn;
        }
        __syncthreads();
    }

    // logits epilogue: 512 outputs, one per thread
    {
        int s = tid >> 3, o = tid & 7;
        float a0 = obs[o], a1 = 0.f;
        const float* r = &outs[s * 68];
        const float* wv = &outw[o * 68];
#pragma unroll
        for (int k = 0; k < 64; k += 2) {
            a0 += r[k] * wv[k];
            a1 += r[k + 1] * wv[k + 1];
        }
        out[(size_t)(b * TT + s) * 8 + o] = a0 + a1;
    }
    if (out_size >= 18432 && tid < 64) out[16384 + b * 64 + tid] = hs[tid];
}

// ---------------------------------------------------------------------------
extern "C" void kernel_launch(void* const* d_in, const int* in_sizes, int n_in,
                              void* d_out, int out_size) {
    const float* x_vis   = (const float*)d_in[0];
    const float* hx      = (const float*)d_in[1];
    const float* conv1_w = (const float*)d_in[2];
    const float* conv1_b = (const float*)d_in[3];
    const float* conv2_w = (const float*)d_in[4];
    const float* conv2_b = (const float*)d_in[5];
    const float* bb_w    = (const float*)d_in[6];
    const float* bb_b    = (const float*)d_in[7];
    const float* ff1_w   = (const float*)d_in[8];
    const float* ff1_b   = (const float*)d_in[9];
    const float* ff2_w   = (const float*)d_in[10];
    const float* ff2_b   = (const float*)d_in[11];
    const float* ta_w    = (const float*)d_in[12];
    const float* ta_b    = (const float*)d_in[13];
    const float* tb_w    = (const float*)d_in[14];
    const float* tb_b    = (const float*)d_in[15];
    const float* out_w   = (const float*)d_in[16];
    const float* out_b   = (const float*)d_in[17];
    float* out = (float*)d_out;

    const size_t smf = CB_TOT;                             // 105824 B (occ 2)

    cudaFuncSetAttribute(fused_conv_kernel, cudaFuncAttributeMaxDynamicSharedMemorySize, (int)smf);

    prep_kernel<<<1026, 256>>>(conv1_w, conv2_w, bb_w);
    fused_conv_kernel<<<NT, 512, smf>>>(x_vis, conv1_b, conv2_b);
    gemm_pre_kernel<<<dim3(16, KSPLIT), 256>>>();
    reduce_kernel<<<256, 256>>>();
    recur_kernel<<<BB, 512>>>(hx, bb_w, bb_b,
                              ff1_w, ff1_b, ff2_w, ff2_b,
                              ta_w, ta_b, tb_w, tb_b,
                              out_w, out_b, out, out_size);
}